// round 1
// baseline (speedup 1.0000x reference)
#include <cuda_runtime.h>
#include <math.h>

#define BB 64
#define LL 500
#define FF 256
#define HH 4
#define DK 64
#define BL (BB*LL)      // 32000
#define BHL (BB*HH*LL)  // 128000

// ---------------- scratch (device globals; no allocation allowed) ----------
__device__ float g_qh[BB*HH*LL*DK];   // [B,H,L,dk]
__device__ float g_vh[BB*HH*LL*DK];   // [B,H,L,dk]
__device__ float g_w [BB*HH*LL*DK];   // weight = relu(qh@w1+b1), [B,H,L,dk]
__device__ float g_o [BB*LL*FF];      // attention out, [B,L,F]
__device__ float g_fc[BB*LL*FF];      // fc out + residual, pre-LN

// ===========================================================================
// K1: projection GEMM  C = A @ W, A [32000,256], W [256,256] row-major
// output permuted into [B,H,L,dk]:  dst[((b*H+h)*L+l)*64 + d]
// blockIdx.x = m-tile (64 rows), blockIdx.y = head h (64 cols)
// ===========================================================================
__global__ void __launch_bounds__(256)
proj_kernel(const float* __restrict__ A, const float* __restrict__ W,
            float* __restrict__ dst)
{
    __shared__ float As[16][64];   // [k][m]
    __shared__ float Bs[16][64];   // [k][n]
    const int m0 = blockIdx.x * 64;
    const int h  = blockIdx.y;
    const int tid = threadIdx.x;
    const int tx = tid & 15, ty = tid >> 4;

    float acc[4][4];
#pragma unroll
    for (int i = 0; i < 4; i++)
#pragma unroll
        for (int j = 0; j < 4; j++) acc[i][j] = 0.f;

    for (int k0 = 0; k0 < 256; k0 += 16) {
        {   // A tile: 64 rows x 16 k, transposed store
            int r = tid >> 2, v = tid & 3;
            float4 a = *(const float4*)&A[(m0 + r) * 256 + k0 + v * 4];
            As[v*4+0][r] = a.x; As[v*4+1][r] = a.y;
            As[v*4+2][r] = a.z; As[v*4+3][r] = a.w;
        }
        {   // B tile: 16 k x 64 n
            int kk = tid >> 4, v = tid & 15;
            *(float4*)&Bs[kk][v*4] = *(const float4*)&W[(k0 + kk) * 256 + h * 64 + v * 4];
        }
        __syncthreads();
#pragma unroll
        for (int kk = 0; kk < 16; kk++) {
            float4 a4 = *(const float4*)&As[kk][ty * 4];
            float4 b4 = *(const float4*)&Bs[kk][tx * 4];
            float a[4] = {a4.x, a4.y, a4.z, a4.w};
            float b[4] = {b4.x, b4.y, b4.z, b4.w};
#pragma unroll
            for (int i = 0; i < 4; i++)
#pragma unroll
                for (int j = 0; j < 4; j++)
                    acc[i][j] = fmaf(a[i], b[j], acc[i][j]);
        }
        __syncthreads();
    }
#pragma unroll
    for (int i = 0; i < 4; i++) {
        int row = m0 + ty * 4 + i;
        int b_  = row / LL;
        int l   = row - b_ * LL;
        float* d = &dst[((b_ * HH + h) * LL + l) * DK + tx * 4];
#pragma unroll
        for (int j = 0; j < 4; j++) d[j] = acc[i][j];
    }
}

// ===========================================================================
// K2: weight = relu(qh @ w1 + b1)   [128000,64]@[64,64]
// ===========================================================================
__global__ void __launch_bounds__(256)
weight_kernel(const float* __restrict__ Qh, const float* __restrict__ w1,
              const float* __restrict__ b1, float* __restrict__ Wout)
{
    __shared__ float As[64][64];   // [k][r]
    __shared__ float Ws[64][64];   // [k][c]
    const int m0 = blockIdx.x * 64;
    const int tid = threadIdx.x;
    const int tx = tid & 15, ty = tid >> 4;

    for (int t = tid; t < 1024; t += 256) {
        int r = t >> 4, v = t & 15;
        float4 a = *(const float4*)&Qh[(m0 + r) * 64 + v * 4];
        As[v*4+0][r] = a.x; As[v*4+1][r] = a.y;
        As[v*4+2][r] = a.z; As[v*4+3][r] = a.w;
    }
    for (int t = tid; t < 1024; t += 256) {
        int k = t >> 4, v = t & 15;
        *(float4*)&Ws[k][v*4] = *(const float4*)&w1[k * 64 + v * 4];
    }
    __syncthreads();

    float acc[4][4];
#pragma unroll
    for (int i = 0; i < 4; i++)
#pragma unroll
        for (int j = 0; j < 4; j++) acc[i][j] = 0.f;

#pragma unroll 16
    for (int k = 0; k < 64; k++) {
        float4 a4 = *(const float4*)&As[k][ty * 4];
        float4 b4 = *(const float4*)&Ws[k][tx * 4];
        float a[4] = {a4.x, a4.y, a4.z, a4.w};
        float b[4] = {b4.x, b4.y, b4.z, b4.w};
#pragma unroll
        for (int i = 0; i < 4; i++)
#pragma unroll
            for (int j = 0; j < 4; j++)
                acc[i][j] = fmaf(a[i], b[j], acc[i][j]);
    }
#pragma unroll
    for (int i = 0; i < 4; i++) {
        int row = m0 + ty * 4 + i;
#pragma unroll
        for (int j = 0; j < 4; j++) {
            float v = acc[i][j] + b1[tx * 4 + j];
            Wout[row * 64 + tx * 4 + j] = v > 0.f ? v : 0.f;
        }
    }
}

// ===========================================================================
// K3: fused dense-synthesizer attention (flash style)
// per (b,h):  S = weight @ w2 + b2 ; P = softmax(S) ; O = P @ vh
// grid = (4 l-tiles of 128, 256 bh), 256 threads
// ===========================================================================
#define TM 128
#define TN 64
#define PSTR 68            // padded row stride for P in smem
#define ATTN_SMEM_FLOATS (64*TM /*Qs*/ + 64*64 /*Ks*/ + 64*64 /*Vs*/ + TM*PSTR /*Ps*/ + 64 /*b2*/)

__global__ void __launch_bounds__(256)
attn_kernel(const float* __restrict__ Wq, const float* __restrict__ Vh,
            const float* __restrict__ w2, const float* __restrict__ b2,
            float* __restrict__ O)
{
    extern __shared__ float sm[];
    float* Qs  = sm;                    // [64][128]  (k-major)
    float* Ks  = Qs + 64 * TM;          // [64][64]   (k x j)
    float* Vs  = Ks + 64 * 64;          // [64][64]   (j x d)
    float* Ps  = Vs + 64 * 64;          // [128][68]  (r x j)
    float* b2s = Ps + TM * PSTR;        // [64]

    const int bh = blockIdx.y;
    const int b_ = bh >> 2, h = bh & 3;
    const int l0 = blockIdx.x * TM;
    const int tid = threadIdx.x;
    const int tx = tid & 15, ty = tid >> 4;

    const float* wbase = Wq + (size_t)bh * LL * DK;
    const float* vbase = Vh + (size_t)bh * LL * DK;

    // load Q tile (transposed to k-major)
    for (int t = tid; t < TM * DK; t += 256) {
        int r = t >> 6, d = t & 63;
        int l = l0 + r;
        Qs[d * TM + r] = (l < LL) ? wbase[l * DK + d] : 0.f;
    }

    float m_[8], lsum[8], acc[8][4];
#pragma unroll
    for (int i = 0; i < 8; i++) {
        m_[i] = -INFINITY; lsum[i] = 0.f;
#pragma unroll
        for (int j = 0; j < 4; j++) acc[i][j] = 0.f;
    }

    for (int jt = 0; jt < 8; jt++) {
        const int j0 = jt * TN;
        __syncthreads();   // prev iter's PV reads + (first iter) Q-load done
        for (int t = tid; t < 64 * 64; t += 256) {
            int d = t >> 6, jj = t & 63;
            int j = j0 + jj;
            Ks[d * 64 + jj] = (j < LL) ? w2[d * LL + j] : 0.f;
        }
        for (int t = tid; t < 64 * 64; t += 256) {
            int jj = t >> 6, d = t & 63;
            int j = j0 + jj;
            Vs[jj * 64 + d] = (j < LL) ? vbase[j * 64 + d] : 0.f;
        }
        if (tid < 64) { int j = j0 + tid; b2s[tid] = (j < LL) ? b2[j] : 0.f; }
        __syncthreads();

        // ---- S = Q @ K ----
        float s[8][4];
#pragma unroll
        for (int i = 0; i < 8; i++)
#pragma unroll
            for (int j = 0; j < 4; j++) s[i][j] = 0.f;

#pragma unroll 8
        for (int k = 0; k < 64; k++) {
            float4 a0 = *(const float4*)&Qs[k * TM + ty * 8];
            float4 a1 = *(const float4*)&Qs[k * TM + ty * 8 + 4];
            float4 b4 = *(const float4*)&Ks[k * 64 + tx * 4];
            float a[8] = {a0.x, a0.y, a0.z, a0.w, a1.x, a1.y, a1.z, a1.w};
            float b[4] = {b4.x, b4.y, b4.z, b4.w};
#pragma unroll
            for (int i = 0; i < 8; i++)
#pragma unroll
                for (int j = 0; j < 4; j++)
                    s[i][j] = fmaf(a[i], b[j], s[i][j]);
        }

        // bias + mask
#pragma unroll
        for (int j = 0; j < 4; j++) {
            int jg = j0 + tx * 4 + j;
            bool valid = jg < LL;
            float bj = valid ? b2s[tx * 4 + j] : 0.f;
#pragma unroll
            for (int i = 0; i < 8; i++)
                s[i][j] = valid ? (s[i][j] + bj) : -1e30f;
        }

        // ---- online softmax ----
#pragma unroll
        for (int i = 0; i < 8; i++) {
            float mt = s[i][0];
#pragma unroll
            for (int j = 1; j < 4; j++) mt = fmaxf(mt, s[i][j]);
#pragma unroll
            for (int o = 1; o < 16; o <<= 1)
                mt = fmaxf(mt, __shfl_xor_sync(0xffffffffu, mt, o));
            float mn = fmaxf(m_[i], mt);
            float scale = __expf(m_[i] - mn);
            float rs = 0.f;
#pragma unroll
            for (int j = 0; j < 4; j++) { s[i][j] = __expf(s[i][j] - mn); rs += s[i][j]; }
#pragma unroll
            for (int o = 1; o < 16; o <<= 1)
                rs += __shfl_xor_sync(0xffffffffu, rs, o);
            lsum[i] = lsum[i] * scale + rs;
            m_[i] = mn;
#pragma unroll
            for (int j = 0; j < 4; j++) acc[i][j] *= scale;
        }

        // write P to smem [r][j]
#pragma unroll
        for (int i = 0; i < 8; i++)
            *(float4*)&Ps[(ty * 8 + i) * PSTR + tx * 4] =
                make_float4(s[i][0], s[i][1], s[i][2], s[i][3]);
        __syncthreads();

        // ---- acc += P @ V ----
#pragma unroll 8
        for (int j = 0; j < 64; j++) {
            float4 b4 = *(const float4*)&Vs[j * 64 + tx * 4];
            float b[4] = {b4.x, b4.y, b4.z, b4.w};
            float pr[8];
#pragma unroll
            for (int i = 0; i < 8; i++) pr[i] = Ps[(ty * 8 + i) * PSTR + j];
#pragma unroll
            for (int i = 0; i < 8; i++)
#pragma unroll
                for (int c = 0; c < 4; c++)
                    acc[i][c] = fmaf(pr[i], b[c], acc[i][c]);
        }
    }

    // epilogue: normalize, store to [B,L,F] with head offset
#pragma unroll
    for (int i = 0; i < 8; i++) {
        int l = l0 + ty * 8 + i;
        if (l < LL) {
            float inv = 1.f / lsum[i];
            float* d = &O[((size_t)(b_ * LL + l)) * FF + h * 64 + tx * 4];
#pragma unroll
            for (int j = 0; j < 4; j++) d[j] = acc[i][j] * inv;
        }
    }
}

// ===========================================================================
// K4: fc GEMM + residual:  g_fc = g_o @ fc_w + q
// ===========================================================================
__global__ void __launch_bounds__(256)
fc_kernel(const float* __restrict__ A, const float* __restrict__ W,
          const float* __restrict__ Res, float* __restrict__ Out)
{
    __shared__ float As[16][64];
    __shared__ float Bs[16][64];
    const int m0 = blockIdx.x * 64;
    const int n0 = blockIdx.y * 64;
    const int tid = threadIdx.x;
    const int tx = tid & 15, ty = tid >> 4;

    float acc[4][4];
#pragma unroll
    for (int i = 0; i < 4; i++)
#pragma unroll
        for (int j = 0; j < 4; j++) acc[i][j] = 0.f;

    for (int k0 = 0; k0 < 256; k0 += 16) {
        {
            int r = tid >> 2, v = tid & 3;
            float4 a = *(const float4*)&A[(m0 + r) * 256 + k0 + v * 4];
            As[v*4+0][r] = a.x; As[v*4+1][r] = a.y;
            As[v*4+2][r] = a.z; As[v*4+3][r] = a.w;
        }
        {
            int kk = tid >> 4, v = tid & 15;
            *(float4*)&Bs[kk][v*4] = *(const float4*)&W[(k0 + kk) * 256 + n0 + v * 4];
        }
        __syncthreads();
#pragma unroll
        for (int kk = 0; kk < 16; kk++) {
            float4 a4 = *(const float4*)&As[kk][ty * 4];
            float4 b4 = *(const float4*)&Bs[kk][tx * 4];
            float a[4] = {a4.x, a4.y, a4.z, a4.w};
            float b[4] = {b4.x, b4.y, b4.z, b4.w};
#pragma unroll
            for (int i = 0; i < 4; i++)
#pragma unroll
                for (int j = 0; j < 4; j++)
                    acc[i][j] = fmaf(a[i], b[j], acc[i][j]);
        }
        __syncthreads();
    }
#pragma unroll
    for (int i = 0; i < 4; i++) {
        int row = m0 + ty * 4 + i;
#pragma unroll
        for (int j = 0; j < 4; j++) {
            int col = n0 + tx * 4 + j;
            Out[(size_t)row * 256 + col] = acc[i][j] + Res[(size_t)row * 256 + col];
        }
    }
}

// ===========================================================================
// K5: LayerNorm over last dim (256), eps=1e-6, two-pass
// 8 warps/block, 1 row per warp, lane owns 8 cols (two float4)
// ===========================================================================
__global__ void __launch_bounds__(256)
ln_kernel(const float* __restrict__ X, const float* __restrict__ gw,
          const float* __restrict__ gb, float* __restrict__ Out)
{
    const int row  = blockIdx.x * 8 + (threadIdx.x >> 5);
    const int lane = threadIdx.x & 31;
    const float* x = X + (size_t)row * 256;

    float4 a = *(const float4*)&x[lane * 4];
    float4 c = *(const float4*)&x[128 + lane * 4];
    float v[8] = {a.x, a.y, a.z, a.w, c.x, c.y, c.z, c.w};

    float sum = 0.f;
#pragma unroll
    for (int i = 0; i < 8; i++) sum += v[i];
#pragma unroll
    for (int o = 16; o; o >>= 1) sum += __shfl_xor_sync(0xffffffffu, sum, o);
    float mu = sum * (1.f / 256.f);

    float vs = 0.f;
#pragma unroll
    for (int i = 0; i < 8; i++) { float d = v[i] - mu; vs += d * d; }
#pragma unroll
    for (int o = 16; o; o >>= 1) vs += __shfl_xor_sync(0xffffffffu, vs, o);
    float rstd = rsqrtf(vs * (1.f / 256.f) + 1e-6f);

    float4 g0 = *(const float4*)&gw[lane * 4];
    float4 g1 = *(const float4*)&gw[128 + lane * 4];
    float4 b0 = *(const float4*)&gb[lane * 4];
    float4 b1 = *(const float4*)&gb[128 + lane * 4];
    float g[8] = {g0.x, g0.y, g0.z, g0.w, g1.x, g1.y, g1.z, g1.w};
    float bb[8] = {b0.x, b0.y, b0.z, b0.w, b1.x, b1.y, b1.z, b1.w};

    float o0[8];
#pragma unroll
    for (int i = 0; i < 8; i++) o0[i] = (v[i] - mu) * rstd * g[i] + bb[i];

    float* y = Out + (size_t)row * 256;
    *(float4*)&y[lane * 4]       = make_float4(o0[0], o0[1], o0[2], o0[3]);
    *(float4*)&y[128 + lane * 4] = make_float4(o0[4], o0[5], o0[6], o0[7]);
}

// ===========================================================================
// launch
// ===========================================================================
extern "C" void kernel_launch(void* const* d_in, const int* in_sizes, int n_in,
                              void* d_out, int out_size)
{
    const float* q    = (const float*)d_in[0];
    // d_in[1] = k, unused by the reference
    const float* v    = (const float*)d_in[2];
    const float* w_qs = (const float*)d_in[3];
    const float* w_vs = (const float*)d_in[4];
    const float* w1   = (const float*)d_in[5];
    const float* b1   = (const float*)d_in[6];
    const float* w2   = (const float*)d_in[7];
    const float* b2   = (const float*)d_in[8];
    const float* fc_w = (const float*)d_in[9];
    const float* ln_g = (const float*)d_in[10];
    const float* ln_b = (const float*)d_in[11];
    float* out = (float*)d_out;

    float *qh, *vh, *wgt, *o, *fc;
    cudaGetSymbolAddress((void**)&qh,  g_qh);
    cudaGetSymbolAddress((void**)&vh,  g_vh);
    cudaGetSymbolAddress((void**)&wgt, g_w);
    cudaGetSymbolAddress((void**)&o,   g_o);
    cudaGetSymbolAddress((void**)&fc,  g_fc);

    const size_t attn_smem = ATTN_SMEM_FLOATS * sizeof(float);   // ~100 KB
    cudaFuncSetAttribute(attn_kernel, cudaFuncAttributeMaxDynamicSharedMemorySize,
                         (int)attn_smem);

    dim3 gProj(BL / 64, HH);                  // (500, 4)
    proj_kernel<<<gProj, 256>>>(q, w_qs, qh);
    proj_kernel<<<gProj, 256>>>(v, w_vs, vh);

    weight_kernel<<<BHL / 64, 256>>>(qh, w1, b1, wgt);

    dim3 gAttn((LL + TM - 1) / TM, BB * HH);  // (4, 256)
    attn_kernel<<<gAttn, 256, attn_smem>>>(wgt, vh, w2, b2, o);

    dim3 gFc(BL / 64, FF / 64);               // (500, 4)
    fc_kernel<<<gFc, 256>>>(o, fc_w, q, fc);

    ln_kernel<<<BL / 8, 256>>>(fc, ln_g, ln_b, out);
}

// round 2
// speedup vs baseline: 1.0744x; 1.0744x over previous
#include <cuda_runtime.h>
#include <math.h>

#define BB 64
#define LL 500
#define FF 256
#define HH 4
#define DK 64
#define BL (BB*LL)      // 32000
#define BHL (BB*HH*LL)  // 128000

typedef unsigned long long u64;

// ---------------- f32x2 packed-math helpers (sm_103a FFMA2 path) ----------
__device__ __forceinline__ u64 dup2(float x) {
    u64 d; unsigned r = __float_as_uint(x);
    asm("mov.b64 %0, {%1, %1};" : "=l"(d) : "r"(r));
    return d;
}
__device__ __forceinline__ void fma2(u64& d, u64 a, u64 b) {
    asm("fma.rn.f32x2 %0, %1, %2, %0;" : "+l"(d) : "l"(a), "l"(b));
}
__device__ __forceinline__ void unpk(u64 v, float& lo, float& hi) {
    unsigned a, b;
    asm("mov.b64 {%0, %1}, %2;" : "=r"(a), "=r"(b) : "l"(v));
    lo = __uint_as_float(a); hi = __uint_as_float(b);
}

// ---------------- scratch (device globals; no allocation allowed) ----------
__device__ float g_qh[BB*HH*LL*DK];   // [B,H,L,dk]
__device__ float g_vh[BB*HH*LL*DK];   // [B,H,L,dk]
__device__ float g_w [BB*HH*LL*DK];   // weight = relu(qh@w1+b1), [B,H,L,dk]
__device__ float g_o [BB*LL*FF];      // attention out, [B,L,F]
__device__ float g_fc[BB*LL*FF];      // fc out + residual, pre-LN

// ===========================================================================
// K1: projection GEMM  C = A @ W, A [32000,256], W [256,256] row-major
// output permuted into [B,H,L,dk].  64x64 tile, kdepth 32, f32x2 math.
// ===========================================================================
__global__ void __launch_bounds__(256)
proj_kernel(const float* __restrict__ A, const float* __restrict__ W,
            float* __restrict__ dst)
{
    __shared__ float As[32*68];   // [k][m], stride 68
    __shared__ float Bs[32*64];   // [k][n]
    const int m0 = blockIdx.x * 64;
    const int h  = blockIdx.y;
    const int tid = threadIdx.x;
    const int tx = tid & 15, ty = tid >> 4;

    u64 acc[4][2];                // [j][row-pair]
#pragma unroll
    for (int j = 0; j < 4; j++) { acc[j][0] = 0; acc[j][1] = 0; }

    for (int k0 = 0; k0 < 256; k0 += 32) {
        // A tile 64x32, transposed -> As[k][r]
#pragma unroll
        for (int it = 0; it < 2; it++) {
            int idx = tid + it * 256;        // 512 float4
            int r = idx >> 3, kv = (idx & 7) * 4;
            float4 a = *(const float4*)&A[(m0 + r) * 256 + k0 + kv];
            As[(kv+0)*68 + r] = a.x; As[(kv+1)*68 + r] = a.y;
            As[(kv+2)*68 + r] = a.z; As[(kv+3)*68 + r] = a.w;
        }
        // B tile 32x64
#pragma unroll
        for (int it = 0; it < 2; it++) {
            int idx = tid + it * 256;
            int kk = idx >> 4, jv = (idx & 15) * 4;
            *(float4*)&Bs[kk*64 + jv] = *(const float4*)&W[(k0 + kk) * 256 + h * 64 + jv];
        }
        __syncthreads();
#pragma unroll 8
        for (int k = 0; k < 32; k++) {
            ulonglong2 a2 = *(const ulonglong2*)&As[k*68 + ty*4];
            float4 b4 = *(const float4*)&Bs[k*64 + tx*4];
            u64 bd[4] = {dup2(b4.x), dup2(b4.y), dup2(b4.z), dup2(b4.w)};
#pragma unroll
            for (int j = 0; j < 4; j++) {
                fma2(acc[j][0], a2.x, bd[j]);
                fma2(acc[j][1], a2.y, bd[j]);
            }
        }
        __syncthreads();
    }
#pragma unroll
    for (int i = 0; i < 4; i++) {
        int row = m0 + ty * 4 + i;
        int b_  = row / LL;
        int l   = row - b_ * LL;
        float o[4];
#pragma unroll
        for (int j = 0; j < 4; j++) {
            float lo, hi; unpk(acc[j][i >> 1], lo, hi);
            o[j] = (i & 1) ? hi : lo;
        }
        *(float4*)&dst[((b_ * HH + h) * LL + l) * DK + tx * 4] =
            make_float4(o[0], o[1], o[2], o[3]);
    }
}

// ===========================================================================
// K2: weight = relu(qh @ w1 + b1)   [128000,64]@[64,64], f32x2
// ===========================================================================
__global__ void __launch_bounds__(256)
weight_kernel(const float* __restrict__ Qh, const float* __restrict__ w1,
              const float* __restrict__ b1, float* __restrict__ Wout)
{
    __shared__ float As[64*68];   // [k][r]
    __shared__ float Ws[64*64];   // [k][c]
    const int m0 = blockIdx.x * 64;
    const int tid = threadIdx.x;
    const int tx = tid & 15, ty = tid >> 4;

#pragma unroll
    for (int it = 0; it < 4; it++) {
        int idx = tid + it * 256;            // 1024 float4
        int r = idx >> 4, kv = (idx & 15) * 4;
        float4 a = *(const float4*)&Qh[(m0 + r) * 64 + kv];
        As[(kv+0)*68 + r] = a.x; As[(kv+1)*68 + r] = a.y;
        As[(kv+2)*68 + r] = a.z; As[(kv+3)*68 + r] = a.w;
    }
#pragma unroll
    for (int it = 0; it < 4; it++) {
        int idx = tid + it * 256;
        int kk = idx >> 4, jv = (idx & 15) * 4;
        *(float4*)&Ws[kk*64 + jv] = *(const float4*)&w1[kk * 64 + jv];
    }
    __syncthreads();

    u64 acc[4][2];
#pragma unroll
    for (int j = 0; j < 4; j++) { acc[j][0] = 0; acc[j][1] = 0; }

#pragma unroll 8
    for (int k = 0; k < 64; k++) {
        ulonglong2 a2 = *(const ulonglong2*)&As[k*68 + ty*4];
        float4 b4 = *(const float4*)&Ws[k*64 + tx*4];
        u64 bd[4] = {dup2(b4.x), dup2(b4.y), dup2(b4.z), dup2(b4.w)};
#pragma unroll
        for (int j = 0; j < 4; j++) {
            fma2(acc[j][0], a2.x, bd[j]);
            fma2(acc[j][1], a2.y, bd[j]);
        }
    }
#pragma unroll
    for (int i = 0; i < 4; i++) {
        int row = m0 + ty * 4 + i;
        float o[4];
#pragma unroll
        for (int j = 0; j < 4; j++) {
            float lo, hi; unpk(acc[j][i >> 1], lo, hi);
            float v = ((i & 1) ? hi : lo) + b1[tx * 4 + j];
            o[j] = v > 0.f ? v : 0.f;
        }
        *(float4*)&Wout[row * 64 + tx * 4] = make_float4(o[0], o[1], o[2], o[3]);
    }
}

// ===========================================================================
// K3: fused dense-synthesizer attention, no-max softmax (logits bounded ~|5|)
// per (b,h):  S = weight @ w2 + b2 ; P = exp(S) ; O = (P @ vh) / rowsum(P)
// 64x64 tiles, f32x2 math, j-packed PV with transposed V.
// grid = (8 l-tiles, 256 bh), 256 threads
// ===========================================================================
#define QSTR 68
#define VSTR 66
#define PSTR 68
#define ATTN_SMEM_FLOATS (64*QSTR + 64*64 + 64*VSTR + 64*PSTR + 64)

__global__ void __launch_bounds__(256)
attn_kernel(const float* __restrict__ Wq, const float* __restrict__ Vh,
            const float* __restrict__ w2, const float* __restrict__ b2,
            float* __restrict__ O)
{
    extern __shared__ float sm[];
    float* Qs  = sm;                    // [64][64] k-major, stride 68
    float* Ks  = Qs + 64 * QSTR;        // [64][64] (k x j)
    float* Vt  = Ks + 64 * 64;          // [64][64] (c x j) transposed, stride 66
    float* Ps  = Vt + 64 * VSTR;        // [64][64] (r x j), stride 68
    float* b2s = Ps + 64 * PSTR;        // [64]

    const int bh = blockIdx.y;
    const int b_ = bh >> 2, h = bh & 3;
    const int l0 = blockIdx.x * 64;
    const int tid = threadIdx.x;
    const int tx = tid & 15, ty = tid >> 4;

    const float* wbase = Wq + (size_t)bh * LL * DK;
    const float* vbase = Vh + (size_t)bh * LL * DK;

    // load Q tile, transposed to k-major (once)
#pragma unroll
    for (int it = 0; it < 4; it++) {
        int idx = tid + it * 256;            // 1024 float4
        int r = idx >> 4, dv = (idx & 15) * 4;
        int l = l0 + r;
        float4 a = (l < LL) ? *(const float4*)&wbase[l * DK + dv]
                            : make_float4(0.f, 0.f, 0.f, 0.f);
        Qs[(dv+0)*QSTR + r] = a.x; Qs[(dv+1)*QSTR + r] = a.y;
        Qs[(dv+2)*QSTR + r] = a.z; Qs[(dv+3)*QSTR + r] = a.w;
    }

    float lsum[4] = {0.f, 0.f, 0.f, 0.f};
    u64 accO[4][4];                     // [row i][c-block cc], packed over j parity
#pragma unroll
    for (int i = 0; i < 4; i++)
#pragma unroll
        for (int c = 0; c < 4; c++) accO[i][c] = 0;

    for (int jt = 0; jt < 8; jt++) {
        const int j0 = jt * 64;
        __syncthreads();   // prev PV reads done (also covers Q-load on iter 0)

        // K tile: Ks[d][jj] = w2[d][j0+jj]   (64x64)
#pragma unroll
        for (int it = 0; it < 4; it++) {
            int idx = tid + it * 256;
            int d = idx >> 4, jv = (idx & 15) * 4;
            float4 v = (j0 + jv < LL) ? *(const float4*)&w2[d * LL + j0 + jv]
                                      : make_float4(0.f, 0.f, 0.f, 0.f);
            *(float4*)&Ks[d*64 + jv] = v;
        }
        // V tile transposed: Vt[c][jj] = vh[j0+jj][c]
#pragma unroll
        for (int it = 0; it < 4; it++) {
            int idx = tid + it * 256;
            int jj = idx >> 4, cv = (idx & 15) * 4;
            int j = j0 + jj;
            float4 v = (j < LL) ? *(const float4*)&vbase[j * DK + cv]
                                : make_float4(0.f, 0.f, 0.f, 0.f);
            Vt[(cv+0)*VSTR + jj] = v.x; Vt[(cv+1)*VSTR + jj] = v.y;
            Vt[(cv+2)*VSTR + jj] = v.z; Vt[(cv+3)*VSTR + jj] = v.w;
        }
        if (tid < 64) { int j = j0 + tid; b2s[tid] = (j < LL) ? b2[j] : 0.f; }
        __syncthreads();

        // ---- S = Q @ K  (f32x2, rows packed) ----
        u64 accS[4][2];
#pragma unroll
        for (int j = 0; j < 4; j++) { accS[j][0] = 0; accS[j][1] = 0; }
#pragma unroll 8
        for (int k = 0; k < 64; k++) {
            ulonglong2 a2 = *(const ulonglong2*)&Qs[k*QSTR + ty*4];
            float4 b4 = *(const float4*)&Ks[k*64 + tx*4];
            u64 bd[4] = {dup2(b4.x), dup2(b4.y), dup2(b4.z), dup2(b4.w)};
#pragma unroll
            for (int j = 0; j < 4; j++) {
                fma2(accS[j][0], a2.x, bd[j]);
                fma2(accS[j][1], a2.y, bd[j]);
            }
        }

        // ---- P = exp(S + b2)  (no max subtraction: logits bounded) ----
        float p[4][4];
#pragma unroll
        for (int j = 0; j < 4; j++) {
            int jg = j0 + tx * 4 + j;
            bool valid = jg < LL;
            float bj = b2s[tx * 4 + j];
            float s0, s1, s2, s3;
            unpk(accS[j][0], s0, s1);
            unpk(accS[j][1], s2, s3);
            p[0][j] = valid ? __expf(s0 + bj) : 0.f;
            p[1][j] = valid ? __expf(s1 + bj) : 0.f;
            p[2][j] = valid ? __expf(s2 + bj) : 0.f;
            p[3][j] = valid ? __expf(s3 + bj) : 0.f;
        }
#pragma unroll
        for (int i = 0; i < 4; i++) {
            lsum[i] += p[i][0] + p[i][1] + p[i][2] + p[i][3];
            *(float4*)&Ps[(ty*4 + i)*PSTR + tx*4] =
                make_float4(p[i][0], p[i][1], p[i][2], p[i][3]);
        }
        __syncthreads();

        // ---- accO += P @ V  (j-packed pairs; V transposed in smem) ----
#pragma unroll 4
        for (int jp = 0; jp < 32; jp++) {
            u64 a0 = *(const u64*)&Ps[(ty*4 + 0)*PSTR + 2*jp];
            u64 a1 = *(const u64*)&Ps[(ty*4 + 1)*PSTR + 2*jp];
            u64 a2 = *(const u64*)&Ps[(ty*4 + 2)*PSTR + 2*jp];
            u64 a3 = *(const u64*)&Ps[(ty*4 + 3)*PSTR + 2*jp];
#pragma unroll
            for (int cc = 0; cc < 4; cc++) {
                u64 b = *(const u64*)&Vt[(tx + 16*cc)*VSTR + 2*jp];
                fma2(accO[0][cc], a0, b);
                fma2(accO[1][cc], a1, b);
                fma2(accO[2][cc], a2, b);
                fma2(accO[3][cc], a3, b);
            }
        }
    }

    // epilogue: reduce lsum across the 16-lane tx group, horizontal-add accO
#pragma unroll
    for (int i = 0; i < 4; i++) {
#pragma unroll
        for (int o = 1; o < 16; o <<= 1)
            lsum[i] += __shfl_xor_sync(0xffffffffu, lsum[i], o);
    }
#pragma unroll
    for (int i = 0; i < 4; i++) {
        int l = l0 + ty * 4 + i;
        if (l < LL) {
            float inv = 1.f / lsum[i];
            float* drow = &O[((size_t)(b_ * LL + l)) * FF + h * 64];
#pragma unroll
            for (int cc = 0; cc < 4; cc++) {
                float lo, hi; unpk(accO[i][cc], lo, hi);
                drow[tx + 16*cc] = (lo + hi) * inv;
            }
        }
    }
}

// ===========================================================================
// K4: fc GEMM + residual:  g_fc = g_o @ fc_w + q   (f32x2, kdepth 32)
// ===========================================================================
__global__ void __launch_bounds__(256)
fc_kernel(const float* __restrict__ A, const float* __restrict__ W,
          const float* __restrict__ Res, float* __restrict__ Out)
{
    __shared__ float As[32*68];
    __shared__ float Bs[32*64];
    const int m0 = blockIdx.x * 64;
    const int n0 = blockIdx.y * 64;
    const int tid = threadIdx.x;
    const int tx = tid & 15, ty = tid >> 4;

    u64 acc[4][2];
#pragma unroll
    for (int j = 0; j < 4; j++) { acc[j][0] = 0; acc[j][1] = 0; }

    for (int k0 = 0; k0 < 256; k0 += 32) {
#pragma unroll
        for (int it = 0; it < 2; it++) {
            int idx = tid + it * 256;
            int r = idx >> 3, kv = (idx & 7) * 4;
            float4 a = *(const float4*)&A[(m0 + r) * 256 + k0 + kv];
            As[(kv+0)*68 + r] = a.x; As[(kv+1)*68 + r] = a.y;
            As[(kv+2)*68 + r] = a.z; As[(kv+3)*68 + r] = a.w;
        }
#pragma unroll
        for (int it = 0; it < 2; it++) {
            int idx = tid + it * 256;
            int kk = idx >> 4, jv = (idx & 15) * 4;
            *(float4*)&Bs[kk*64 + jv] = *(const float4*)&W[(k0 + kk) * 256 + n0 + jv];
        }
        __syncthreads();
#pragma unroll 8
        for (int k = 0; k < 32; k++) {
            ulonglong2 a2 = *(const ulonglong2*)&As[k*68 + ty*4];
            float4 b4 = *(const float4*)&Bs[k*64 + tx*4];
            u64 bd[4] = {dup2(b4.x), dup2(b4.y), dup2(b4.z), dup2(b4.w)};
#pragma unroll
            for (int j = 0; j < 4; j++) {
                fma2(acc[j][0], a2.x, bd[j]);
                fma2(acc[j][1], a2.y, bd[j]);
            }
        }
        __syncthreads();
    }
#pragma unroll
    for (int i = 0; i < 4; i++) {
        int row = m0 + ty * 4 + i;
        float4 r4 = *(const float4*)&Res[(size_t)row * 256 + n0 + tx * 4];
        float o[4];
#pragma unroll
        for (int j = 0; j < 4; j++) {
            float lo, hi; unpk(acc[j][i >> 1], lo, hi);
            o[j] = ((i & 1) ? hi : lo);
        }
        *(float4*)&Out[(size_t)row * 256 + n0 + tx * 4] =
            make_float4(o[0] + r4.x, o[1] + r4.y, o[2] + r4.z, o[3] + r4.w);
    }
}

// ===========================================================================
// K5: LayerNorm over last dim (256), eps=1e-6
// ===========================================================================
__global__ void __launch_bounds__(256)
ln_kernel(const float* __restrict__ X, const float* __restrict__ gw,
          const float* __restrict__ gb, float* __restrict__ Out)
{
    const int row  = blockIdx.x * 8 + (threadIdx.x >> 5);
    const int lane = threadIdx.x & 31;
    const float* x = X + (size_t)row * 256;

    float4 a = *(const float4*)&x[lane * 4];
    float4 c = *(const float4*)&x[128 + lane * 4];
    float v[8] = {a.x, a.y, a.z, a.w, c.x, c.y, c.z, c.w};

    float sum = 0.f;
#pragma unroll
    for (int i = 0; i < 8; i++) sum += v[i];
#pragma unroll
    for (int o = 16; o; o >>= 1) sum += __shfl_xor_sync(0xffffffffu, sum, o);
    float mu = sum * (1.f / 256.f);

    float vs = 0.f;
#pragma unroll
    for (int i = 0; i < 8; i++) { float d = v[i] - mu; vs += d * d; }
#pragma unroll
    for (int o = 16; o; o >>= 1) vs += __shfl_xor_sync(0xffffffffu, vs, o);
    float rstd = rsqrtf(vs * (1.f / 256.f) + 1e-6f);

    float4 g0 = *(const float4*)&gw[lane * 4];
    float4 g1 = *(const float4*)&gw[128 + lane * 4];
    float4 b0 = *(const float4*)&gb[lane * 4];
    float4 b1 = *(const float4*)&gb[128 + lane * 4];
    float g[8] = {g0.x, g0.y, g0.z, g0.w, g1.x, g1.y, g1.z, g1.w};
    float bb[8] = {b0.x, b0.y, b0.z, b0.w, b1.x, b1.y, b1.z, b1.w};

    float o0[8];
#pragma unroll
    for (int i = 0; i < 8; i++) o0[i] = (v[i] - mu) * rstd * g[i] + bb[i];

    float* y = Out + (size_t)row * 256;
    *(float4*)&y[lane * 4]       = make_float4(o0[0], o0[1], o0[2], o0[3]);
    *(float4*)&y[128 + lane * 4] = make_float4(o0[4], o0[5], o0[6], o0[7]);
}

// ===========================================================================
// launch
// ===========================================================================
extern "C" void kernel_launch(void* const* d_in, const int* in_sizes, int n_in,
                              void* d_out, int out_size)
{
    const float* q    = (const float*)d_in[0];
    // d_in[1] = k, unused by the reference
    const float* v    = (const float*)d_in[2];
    const float* w_qs = (const float*)d_in[3];
    const float* w_vs = (const float*)d_in[4];
    const float* w1   = (const float*)d_in[5];
    const float* b1   = (const float*)d_in[6];
    const float* w2   = (const float*)d_in[7];
    const float* b2   = (const float*)d_in[8];
    const float* fc_w = (const float*)d_in[9];
    const float* ln_g = (const float*)d_in[10];
    const float* ln_b = (const float*)d_in[11];
    float* out = (float*)d_out;

    float *qh, *vh, *wgt, *o, *fc;
    cudaGetSymbolAddress((void**)&qh,  g_qh);
    cudaGetSymbolAddress((void**)&vh,  g_vh);
    cudaGetSymbolAddress((void**)&wgt, g_w);
    cudaGetSymbolAddress((void**)&o,   g_o);
    cudaGetSymbolAddress((void**)&fc,  g_fc);

    const size_t attn_smem = ATTN_SMEM_FLOATS * sizeof(float);   // ~68 KB
    cudaFuncSetAttribute(attn_kernel, cudaFuncAttributeMaxDynamicSharedMemorySize,
                         (int)attn_smem);

    dim3 gProj(BL / 64, HH);                  // (500, 4)
    proj_kernel<<<gProj, 256>>>(q, w_qs, qh);
    proj_kernel<<<gProj, 256>>>(v, w_vs, vh);

    weight_kernel<<<BHL / 64, 256>>>(qh, w1, b1, wgt);

    dim3 gAttn(8, BB * HH);                   // (8, 256)
    attn_kernel<<<gAttn, 256, attn_smem>>>(wgt, vh, w2, b2, o);

    dim3 gFc(BL / 64, FF / 64);               // (500, 4)
    fc_kernel<<<gFc, 256>>>(o, fc_w, q, fc);

    ln_kernel<<<BL / 8, 256>>>(fc, ln_g, ln_b, out);
}

// round 3
// speedup vs baseline: 1.1245x; 1.0466x over previous
#include <cuda_runtime.h>
#include <math.h>

#define BB 64
#define LL 500
#define FF 256
#define HH 4
#define DK 64
#define BL (BB*LL)      // 32000

typedef unsigned long long u64;

// ---------------- f32x2 packed-math helpers (sm_103a FFMA2 path) ----------
__device__ __forceinline__ u64 dup2(float x) {
    u64 d; unsigned r = __float_as_uint(x);
    asm("mov.b64 %0, {%1, %1};" : "=l"(d) : "r"(r));
    return d;
}
__device__ __forceinline__ void fma2(u64& d, u64 a, u64 b) {
    asm("fma.rn.f32x2 %0, %1, %2, %0;" : "+l"(d) : "l"(a), "l"(b));
}
__device__ __forceinline__ void unpk(u64 v, float& lo, float& hi) {
    unsigned a, b;
    asm("mov.b64 {%0, %1}, %2;" : "=r"(a), "=r"(b) : "l"(v));
    lo = __uint_as_float(a); hi = __uint_as_float(b);
}

// ---------------- scratch ----------------
__device__ float g_w [BB*HH*LL*DK];   // weight = relu(q@Wcomb+b1), [B,H,L,dk]
__device__ float g_vh[BB*HH*LL*DK];   // [B,H,L,dk]
__device__ float g_o [BB*LL*FF];      // attention out, [B,L,F]
__device__ float g_wc[FF*FF];         // Wcomb = w_qs . blockdiag(w1)

// ===========================================================================
// K0: Wcomb[f, h*64+d] = sum_e w_qs[f, h*64+e] * w1[e, d]
// ===========================================================================
__global__ void __launch_bounds__(256)
wcomb_kernel(const float* __restrict__ wqs, const float* __restrict__ w1,
             float* __restrict__ wc)
{
    __shared__ float w1s[64*64];
    const int tid = threadIdx.x;
    for (int i = tid; i < 4096; i += 256) w1s[i] = w1[i];
    __syncthreads();
    const int d = tid & 63, sub = tid >> 6;
    const int f = blockIdx.x * 4 + sub;
#pragma unroll
    for (int h = 0; h < 4; h++) {
        float acc = 0.f;
        const float* wr = &wqs[f*256 + h*64];
#pragma unroll 8
        for (int e = 0; e < 64; e++)
            acc = fmaf(wr[e], w1s[e*64 + d], acc);
        wc[f*256 + h*64 + d] = acc;
    }
}

// ===========================================================================
// K1: projection GEMM  C = op(A @ W [+ bias]) permuted into [B,H,L,dk]
// tile 64 rows x 256 cols, 256 threads, 8x8 per thread (row-pair packed f32x2)
// tx = tid&31 -> cols tx*8..+7 ; ty = tid>>5 -> rows ty*8..+7
// ===========================================================================
template<bool RELU>
__global__ void __launch_bounds__(256)
proj_kernel(const float* __restrict__ A, const float* __restrict__ W,
            const float* __restrict__ bias, float* __restrict__ dst)
{
    __shared__ float As[32*68];     // [k][r] k-major, stride 68
    __shared__ float Bs[32*256];    // [k][c]
    const int m0 = blockIdx.x * 64;
    const int tid = threadIdx.x;
    const int tx = tid & 31, ty = tid >> 5;

    u64 acc[4][8];
#pragma unroll
    for (int m = 0; m < 4; m++)
#pragma unroll
        for (int j = 0; j < 8; j++) acc[m][j] = 0;

    for (int k0 = 0; k0 < 256; k0 += 32) {
        // A tile 64r x 32k transposed
#pragma unroll
        for (int it = 0; it < 2; it++) {
            int fidx = tid + it * 256;           // 512 float4
            int r = fidx >> 3, kv = (fidx & 7) * 4;
            float4 a = *(const float4*)&A[(m0 + r) * 256 + k0 + kv];
            As[(kv+0)*68 + r] = a.x; As[(kv+1)*68 + r] = a.y;
            As[(kv+2)*68 + r] = a.z; As[(kv+3)*68 + r] = a.w;
        }
        // B tile 32k x 256c
#pragma unroll
        for (int it = 0; it < 8; it++) {
            int fidx = tid + it * 256;           // 2048 float4
            int kk = fidx >> 6, c4 = (fidx & 63) * 4;
            *(float4*)&Bs[kk*256 + c4] = *(const float4*)&W[(k0 + kk) * 256 + c4];
        }
        __syncthreads();
#pragma unroll 2
        for (int k = 0; k < 32; k++) {
            ulonglong2 q01 = *(const ulonglong2*)&As[k*68 + ty*8];
            ulonglong2 q23 = *(const ulonglong2*)&As[k*68 + ty*8 + 4];
            float4 b0 = *(const float4*)&Bs[k*256 + tx*8];
            float4 b1 = *(const float4*)&Bs[k*256 + tx*8 + 4];
            u64 qp[4] = {q01.x, q01.y, q23.x, q23.y};
            u64 bd[8] = {dup2(b0.x), dup2(b0.y), dup2(b0.z), dup2(b0.w),
                         dup2(b1.x), dup2(b1.y), dup2(b1.z), dup2(b1.w)};
#pragma unroll
            for (int m = 0; m < 4; m++)
#pragma unroll
                for (int j = 0; j < 8; j++)
                    fma2(acc[m][j], qp[m], bd[j]);
        }
        __syncthreads();
    }

    // epilogue: permute to [B,H,L,dk]
    const int h = tx >> 3;
    const int d0 = (tx & 7) * 8;
#pragma unroll
    for (int m = 0; m < 4; m++) {
        float lo[8], hi[8];
#pragma unroll
        for (int j = 0; j < 8; j++) unpk(acc[m][j], lo[j], hi[j]);
#pragma unroll
        for (int e = 0; e < 2; e++) {
            int row = m0 + ty * 8 + 2*m + e;
            int b_  = row / LL;
            int l   = row - b_ * LL;
            float* src = e ? hi : lo;
            float o[8];
#pragma unroll
            for (int j = 0; j < 8; j++) {
                float v = src[j];
                if (RELU) { v += bias[d0 + j]; v = v > 0.f ? v : 0.f; }
                o[j] = v;
            }
            float* dp = &dst[((size_t)((b_ * HH + h) * LL + l)) * DK + d0];
            *(float4*)&dp[0] = make_float4(o[0], o[1], o[2], o[3]);
            *(float4*)&dp[4] = make_float4(o[4], o[5], o[6], o[7]);
        }
    }
}

// ===========================================================================
// K2: fused dense-synthesizer attention
// per (b,h):  S = weight @ w2 + b2 ; P = exp(S) ; O = (P @ vh) / rowsum(P)
// 128 l-rows x 128 j-cols per iteration, 4 j-iterations. 256 thr, 8x8/thread.
// tx = tid&15 -> j-cols tx*8..+7 ; ty = tid>>4 -> rows ty*8..+7
// ===========================================================================
#define QS_STR 132
#define KS_STR 128
#define PS_STR 132
#define VS_STR 68
#define ATTN_SMEM_FLOATS (64*QS_STR + 64*KS_STR + 128*PS_STR + 128*VS_STR + 128)

__global__ void __launch_bounds__(256)
attn_kernel(const float* __restrict__ Wq, const float* __restrict__ Vh,
            const float* __restrict__ w2, const float* __restrict__ b2,
            float* __restrict__ O)
{
    extern __shared__ float sm[];
    float* Qs  = sm;                    // [64 k][128 r] stride 132
    float* Ks  = Qs + 64*QS_STR;        // [64 k][128 j]
    float* Ps  = Ks + 64*KS_STR;        // [128 j][128 r] stride 132, XOR-8 swizzle
    float* Vs  = Ps + 128*PS_STR;       // [128 j][64 c] stride 68
    float* b2s = Vs + 128*VS_STR;       // [128]

    const int bh = blockIdx.y;
    const int b_ = bh >> 2, h = bh & 3;
    const int l0 = blockIdx.x * 128;
    const int tid = threadIdx.x;
    const int tx = tid & 15, ty = tid >> 4;

    const float* wbase = Wq + (size_t)bh * LL * DK;
    const float* vbase = Vh + (size_t)bh * LL * DK;

    // load Q tile once, transposed to k-major
#pragma unroll
    for (int it = 0; it < 8; it++) {
        int fidx = tid + it * 256;               // 2048 float4
        int r = fidx >> 4, dv = (fidx & 15) * 4;
        int l = l0 + r;
        float4 a = (l < LL) ? *(const float4*)&wbase[l * DK + dv]
                            : make_float4(0.f, 0.f, 0.f, 0.f);
        Qs[(dv+0)*QS_STR + r] = a.x; Qs[(dv+1)*QS_STR + r] = a.y;
        Qs[(dv+2)*QS_STR + r] = a.z; Qs[(dv+3)*QS_STR + r] = a.w;
    }

    float lsum[8] = {0.f,0.f,0.f,0.f,0.f,0.f,0.f,0.f};
    u64 accO[8][2];
#pragma unroll
    for (int i = 0; i < 8; i++) { accO[i][0] = 0; accO[i][1] = 0; }

    for (int jt = 0; jt < 4; jt++) {
        const int j0 = jt * 128;
        __syncthreads();   // prev PV done reading Ks/Vs/Ps; Qs ready (iter 0)

        // Ks[d][jj] = w2[d][j0+jj]
#pragma unroll
        for (int it = 0; it < 8; it++) {
            int fidx = tid + it * 256;
            int d = fidx >> 5, j4 = (fidx & 31) * 4;
            float4 v = (j0 + j4 < LL) ? *(const float4*)&w2[d * LL + j0 + j4]
                                      : make_float4(0.f, 0.f, 0.f, 0.f);
            *(float4*)&Ks[d*KS_STR + j4] = v;
        }
        // Vs[jj][c] = vh[j0+jj][c]
#pragma unroll
        for (int it = 0; it < 8; it++) {
            int fidx = tid + it * 256;
            int j = fidx >> 4, c4 = (fidx & 15) * 4;
            float4 v = (j0 + j < LL) ? *(const float4*)&vbase[(j0 + j) * DK + c4]
                                     : make_float4(0.f, 0.f, 0.f, 0.f);
            *(float4*)&Vs[j*VS_STR + c4] = v;
        }
        if (tid < 128) { int j = j0 + tid; b2s[tid] = (j < LL) ? b2[j] : 0.f; }
        __syncthreads();

        // ---- S = Q @ K : accS[row-pair m][j] ----
        u64 accS[4][8];
#pragma unroll
        for (int m = 0; m < 4; m++)
#pragma unroll
            for (int j = 0; j < 8; j++) accS[m][j] = 0;

#pragma unroll 2
        for (int k = 0; k < 64; k++) {
            ulonglong2 q01 = *(const ulonglong2*)&Qs[k*QS_STR + ty*8];
            ulonglong2 q23 = *(const ulonglong2*)&Qs[k*QS_STR + ty*8 + 4];
            float4 k0v = *(const float4*)&Ks[k*KS_STR + tx*8];
            float4 k1v = *(const float4*)&Ks[k*KS_STR + tx*8 + 4];
            u64 qp[4] = {q01.x, q01.y, q23.x, q23.y};
            u64 kd[8] = {dup2(k0v.x), dup2(k0v.y), dup2(k0v.z), dup2(k0v.w),
                         dup2(k1v.x), dup2(k1v.y), dup2(k1v.z), dup2(k1v.w)};
#pragma unroll
            for (int m = 0; m < 4; m++)
#pragma unroll
                for (int j = 0; j < 8; j++)
                    fma2(accS[m][j], qp[m], kd[j]);
        }

        // ---- P = exp(S + b2), masked; accumulate lsum; store swizzled ----
        {
            const int pr = (ty * 8) ^ (8 * tx);   // XOR-8 swizzle (j>>3 == tx)
#pragma unroll
            for (int jj = 0; jj < 8; jj++) {
                int jl = tx * 8 + jj;
                bool valid = (j0 + jl) < LL;
                float bj = b2s[jl];
                float p[8];
#pragma unroll
                for (int m = 0; m < 4; m++) {
                    float lo, hi; unpk(accS[m][jj], lo, hi);
                    p[2*m]   = valid ? __expf(lo + bj) : 0.f;
                    p[2*m+1] = valid ? __expf(hi + bj) : 0.f;
                }
#pragma unroll
                for (int i = 0; i < 8; i++) lsum[i] += p[i];
                *(float4*)&Ps[jl*PS_STR + pr]     = make_float4(p[0], p[1], p[2], p[3]);
                *(float4*)&Ps[jl*PS_STR + pr + 4] = make_float4(p[4], p[5], p[6], p[7]);
            }
        }
        __syncthreads();

        // ---- accO += P @ V ----
#pragma unroll 4
        for (int j = 0; j < 128; j++) {
            int prj = (ty * 8) ^ (8 * (j >> 3));
            float4 p0 = *(const float4*)&Ps[j*PS_STR + prj];
            float4 p1 = *(const float4*)&Ps[j*PS_STR + prj + 4];
            ulonglong2 vv = *(const ulonglong2*)&Vs[j*VS_STR + tx*4];
            u64 pd[8] = {dup2(p0.x), dup2(p0.y), dup2(p0.z), dup2(p0.w),
                         dup2(p1.x), dup2(p1.y), dup2(p1.z), dup2(p1.w)};
#pragma unroll
            for (int i = 0; i < 8; i++) {
                fma2(accO[i][0], pd[i], vv.x);
                fma2(accO[i][1], pd[i], vv.y);
            }
        }
    }

    // epilogue: reduce lsum across the 16-lane tx group, normalize, store
#pragma unroll
    for (int i = 0; i < 8; i++) {
#pragma unroll
        for (int o = 1; o < 16; o <<= 1)
            lsum[i] += __shfl_xor_sync(0xffffffffu, lsum[i], o);
    }
#pragma unroll
    for (int i = 0; i < 8; i++) {
        int l = l0 + ty * 8 + i;
        if (l < LL) {
            float inv = 1.f / lsum[i];
            float c0, c1, c2, c3;
            unpk(accO[i][0], c0, c1);
            unpk(accO[i][1], c2, c3);
            *(float4*)&O[((size_t)(b_ * LL + l)) * FF + h * 64 + tx * 4] =
                make_float4(c0 * inv, c1 * inv, c2 * inv, c3 * inv);
        }
    }
}

// ===========================================================================
// K3: fused fc GEMM + residual + LayerNorm -> out
// tile 64 rows x 256 cols; tx = tid&31 (cols tx*8), ty = tid>>5 (rows ty*8..+7)
// warp == row group -> LN via full-warp shfl
// ===========================================================================
__global__ void __launch_bounds__(256)
fc_ln_kernel(const float* __restrict__ A, const float* __restrict__ W,
             const float* __restrict__ Res, const float* __restrict__ lng,
             const float* __restrict__ lnb, float* __restrict__ Out)
{
    __shared__ float As[32*68];
    __shared__ float Bs[32*256];
    const int m0 = blockIdx.x * 64;
    const int tid = threadIdx.x;
    const int tx = tid & 31, ty = tid >> 5;

    u64 acc[4][8];
#pragma unroll
    for (int m = 0; m < 4; m++)
#pragma unroll
        for (int j = 0; j < 8; j++) acc[m][j] = 0;

    for (int k0 = 0; k0 < 256; k0 += 32) {
#pragma unroll
        for (int it = 0; it < 2; it++) {
            int fidx = tid + it * 256;
            int r = fidx >> 3, kv = (fidx & 7) * 4;
            float4 a = *(const float4*)&A[(m0 + r) * 256 + k0 + kv];
            As[(kv+0)*68 + r] = a.x; As[(kv+1)*68 + r] = a.y;
            As[(kv+2)*68 + r] = a.z; As[(kv+3)*68 + r] = a.w;
        }
#pragma unroll
        for (int it = 0; it < 8; it++) {
            int fidx = tid + it * 256;
            int kk = fidx >> 6, c4 = (fidx & 63) * 4;
            *(float4*)&Bs[kk*256 + c4] = *(const float4*)&W[(k0 + kk) * 256 + c4];
        }
        __syncthreads();
#pragma unroll 2
        for (int k = 0; k < 32; k++) {
            ulonglong2 q01 = *(const ulonglong2*)&As[k*68 + ty*8];
            ulonglong2 q23 = *(const ulonglong2*)&As[k*68 + ty*8 + 4];
            float4 b0 = *(const float4*)&Bs[k*256 + tx*8];
            float4 b1 = *(const float4*)&Bs[k*256 + tx*8 + 4];
            u64 qp[4] = {q01.x, q01.y, q23.x, q23.y};
            u64 bd[8] = {dup2(b0.x), dup2(b0.y), dup2(b0.z), dup2(b0.w),
                         dup2(b1.x), dup2(b1.y), dup2(b1.z), dup2(b1.w)};
#pragma unroll
            for (int m = 0; m < 4; m++)
#pragma unroll
                for (int j = 0; j < 8; j++)
                    fma2(acc[m][j], qp[m], bd[j]);
        }
        __syncthreads();
    }

    // epilogue: +residual, LayerNorm per row (row spans one warp), store
    float4 g0 = *(const float4*)&lng[tx*8];
    float4 g1 = *(const float4*)&lng[tx*8 + 4];
    float4 bb0 = *(const float4*)&lnb[tx*8];
    float4 bb1 = *(const float4*)&lnb[tx*8 + 4];
    float g[8]  = {g0.x, g0.y, g0.z, g0.w, g1.x, g1.y, g1.z, g1.w};
    float lb[8] = {bb0.x, bb0.y, bb0.z, bb0.w, bb1.x, bb1.y, bb1.z, bb1.w};

#pragma unroll
    for (int m = 0; m < 4; m++) {
        float lo[8], hi[8];
#pragma unroll
        for (int j = 0; j < 8; j++) unpk(acc[m][j], lo[j], hi[j]);
#pragma unroll
        for (int e = 0; e < 2; e++) {
            int row = m0 + ty * 8 + 2*m + e;
            const float* rp = &Res[(size_t)row * 256 + tx*8];
            float4 r0 = *(const float4*)&rp[0];
            float4 r1 = *(const float4*)&rp[4];
            float* src = e ? hi : lo;
            float v[8] = {src[0]+r0.x, src[1]+r0.y, src[2]+r0.z, src[3]+r0.w,
                          src[4]+r1.x, src[5]+r1.y, src[6]+r1.z, src[7]+r1.w};
            float s = 0.f;
#pragma unroll
            for (int j = 0; j < 8; j++) s += v[j];
#pragma unroll
            for (int o = 16; o; o >>= 1) s += __shfl_xor_sync(0xffffffffu, s, o);
            float mu = s * (1.f / 256.f);
            float vs = 0.f;
#pragma unroll
            for (int j = 0; j < 8; j++) { float d = v[j] - mu; vs += d * d; }
#pragma unroll
            for (int o = 16; o; o >>= 1) vs += __shfl_xor_sync(0xffffffffu, vs, o);
            float rstd = rsqrtf(vs * (1.f / 256.f) + 1e-6f);
            float o8[8];
#pragma unroll
            for (int j = 0; j < 8; j++) o8[j] = (v[j] - mu) * rstd * g[j] + lb[j];
            float* op = &Out[(size_t)row * 256 + tx*8];
            *(float4*)&op[0] = make_float4(o8[0], o8[1], o8[2], o8[3]);
            *(float4*)&op[4] = make_float4(o8[4], o8[5], o8[6], o8[7]);
        }
    }
}

// ===========================================================================
// launch
// ===========================================================================
extern "C" void kernel_launch(void* const* d_in, const int* in_sizes, int n_in,
                              void* d_out, int out_size)
{
    const float* q    = (const float*)d_in[0];
    // d_in[1] = k, unused by the reference
    const float* v    = (const float*)d_in[2];
    const float* w_qs = (const float*)d_in[3];
    const float* w_vs = (const float*)d_in[4];
    const float* w1   = (const float*)d_in[5];
    const float* b1   = (const float*)d_in[6];
    const float* w2   = (const float*)d_in[7];
    const float* b2   = (const float*)d_in[8];
    const float* fc_w = (const float*)d_in[9];
    const float* ln_g = (const float*)d_in[10];
    const float* ln_b = (const float*)d_in[11];
    float* out = (float*)d_out;

    float *wgt, *vh, *o, *wc;
    cudaGetSymbolAddress((void**)&wgt, g_w);
    cudaGetSymbolAddress((void**)&vh,  g_vh);
    cudaGetSymbolAddress((void**)&o,   g_o);
    cudaGetSymbolAddress((void**)&wc,  g_wc);

    const size_t attn_smem = ATTN_SMEM_FLOATS * sizeof(float);   // ~166 KB
    cudaFuncSetAttribute(attn_kernel, cudaFuncAttributeMaxDynamicSharedMemorySize,
                         (int)attn_smem);

    wcomb_kernel<<<64, 256>>>(w_qs, w1, wc);

    proj_kernel<true ><<<BL / 64, 256>>>(q, wc,   b1, wgt);   // weight = relu(q@Wcomb+b1)
    proj_kernel<false><<<BL / 64, 256>>>(v, w_vs, b1, vh);    // vh = v@w_vs

    dim3 gAttn(4, BB * HH);                   // (4 l-tiles, 256 bh)
    attn_kernel<<<gAttn, 256, attn_smem>>>(wgt, vh, w2, b2, o);

    fc_ln_kernel<<<BL / 64, 256>>>(o, fc_w, q, ln_g, ln_b, out);
}

// round 7
// speedup vs baseline: 1.5731x; 1.3989x over previous
#include <cuda_runtime.h>
#include <cuda_bf16.h>
#include <math.h>

#define BB 64
#define LL 500
#define FF 256
#define HH 4
#define DK 64
#define BL (BB*LL)      // 32000
#define LP 512          // padded seq len

typedef unsigned long long u64;
typedef unsigned int u32;

// ---------------- f32x2 packed-math helpers (scalar GEMM path) ----------
__device__ __forceinline__ u64 dup2(float x) {
    u64 d; unsigned r = __float_as_uint(x);
    asm("mov.b64 %0, {%1, %1};" : "=l"(d) : "r"(r));
    return d;
}
__device__ __forceinline__ void fma2(u64& d, u64 a, u64 b) {
    asm("fma.rn.f32x2 %0, %1, %2, %0;" : "+l"(d) : "l"(a), "l"(b));
}
__device__ __forceinline__ void unpk(u64 v, float& lo, float& hi) {
    unsigned a, b;
    asm("mov.b64 {%0, %1}, %2;" : "=r"(a), "=r"(b) : "l"(v));
    lo = __uint_as_float(a); hi = __uint_as_float(b);
}

// ---------------- bf16 pack/split helpers ----------------
__device__ __forceinline__ u32 packbf(float f0, float f1) {
    u32 d; asm("cvt.rn.bf16x2.f32 %0, %1, %2;" : "=r"(d) : "f"(f1), "f"(f0));
    return d;   // low half = f0
}
__device__ __forceinline__ float bflo(u32 d) { return __uint_as_float(d << 16); }
__device__ __forceinline__ float bfhi(u32 d) { return __uint_as_float(d & 0xffff0000u); }
// split 8 floats into hi/lo bf16x2 quads
__device__ __forceinline__ void split8(const float* v, u32* hp, u32* lp) {
#pragma unroll
    for (int i = 0; i < 4; i++) {
        u32 h = packbf(v[2*i], v[2*i+1]);
        hp[i] = h;
        lp[i] = packbf(v[2*i] - bflo(h), v[2*i+1] - bfhi(h));
    }
}

// ---------------- HMMA helpers ----------------
__device__ __forceinline__ void mma_bf16(float* d, const u32* a, u32 b0, u32 b1) {
    asm volatile(
        "mma.sync.aligned.m16n8k16.row.col.f32.bf16.bf16.f32 "
        "{%0,%1,%2,%3}, {%4,%5,%6,%7}, {%8,%9}, {%0,%1,%2,%3};"
        : "+f"(d[0]), "+f"(d[1]), "+f"(d[2]), "+f"(d[3])
        : "r"(a[0]), "r"(a[1]), "r"(a[2]), "r"(a[3]), "r"(b0), "r"(b1));
}
__device__ __forceinline__ void ldsm4(u32* r, u32 addr) {
    asm volatile("ldmatrix.sync.aligned.m8n8.x4.shared.b16 {%0,%1,%2,%3}, [%4];"
        : "=r"(r[0]), "=r"(r[1]), "=r"(r[2]), "=r"(r[3]) : "r"(addr));
}
__device__ __forceinline__ void ldsm4t(u32* r, u32 addr) {
    asm volatile("ldmatrix.sync.aligned.m8n8.x4.trans.shared.b16 {%0,%1,%2,%3}, [%4];"
        : "=r"(r[0]), "=r"(r[1]), "=r"(r[2]), "=r"(r[3]) : "r"(addr));
}
__device__ __forceinline__ u32 smem_u32(const void* p) {
    u32 a;
    asm("{ .reg .u64 t; cvta.to.shared.u64 t, %1; cvt.u32.u64 %0, t; }"
        : "=r"(a) : "l"(p));
    return a;
}

// ---------------- scratch ----------------
__device__ __nv_bfloat16 g_wh [BB*HH*LP*DK];  // weight hi, [bh][512][64]
__device__ __nv_bfloat16 g_wl [BB*HH*LP*DK];  // weight lo
__device__ __nv_bfloat16 g_vhh[BB*HH*LP*DK];  // vh hi
__device__ __nv_bfloat16 g_vhl[BB*HH*LP*DK];  // vh lo
__device__ __nv_bfloat16 g_w2h[LP*DK];        // w2^T hi, [j 512][d 64]
__device__ __nv_bfloat16 g_w2l[LP*DK];        // w2^T lo
__device__ float g_o [BB*LL*FF];              // attention out, [B,L,F]
__device__ float g_wc[FF*FF];                 // Wcomb = w_qs . blockdiag(w1)

// ===========================================================================
// K0: Wcomb[f, h*64+d] = sum_e w_qs[f, h*64+e] * w1[e, d]
// ===========================================================================
__global__ void __launch_bounds__(256)
wcomb_kernel(const float* __restrict__ wqs, const float* __restrict__ w1,
             float* __restrict__ wc)
{
    __shared__ float w1s[64*64];
    const int tid = threadIdx.x;
    for (int i = tid; i < 4096; i += 256) w1s[i] = w1[i];
    __syncthreads();
    const int d = tid & 63, sub = tid >> 6;
    const int f = blockIdx.x * 4 + sub;
#pragma unroll
    for (int h = 0; h < 4; h++) {
        float acc = 0.f;
        const float* wr = &wqs[f*256 + h*64];
#pragma unroll 8
        for (int e = 0; e < 64; e++)
            acc = fmaf(wr[e], w1s[e*64 + d], acc);
        wc[f*256 + h*64 + d] = acc;
    }
}

// ===========================================================================
// K0b: w2 transpose + bf16 split:  g_w2h/l[j][d] = split(w2[d][j]), j>=500 -> 0
// ===========================================================================
__global__ void __launch_bounds__(256)
w2prep_kernel(const float* __restrict__ w2,
              __nv_bfloat16* __restrict__ dh, __nv_bfloat16* __restrict__ dl)
{
    int idx = blockIdx.x * 256 + threadIdx.x;   // 512*64 total
    int j = idx >> 6, d = idx & 63;
    float x = (j < LL) ? w2[d * LL + j] : 0.f;
    __nv_bfloat16 hb = __float2bfloat16(x);
    dh[idx] = hb;
    dl[idx] = __float2bfloat16(x - __bfloat162float(hb));
}

// ===========================================================================
// K1: projection GEMM (scalar f32x2) -> bf16 hi/lo split, [bh][512][64]
// ===========================================================================
template<bool RELU>
__global__ void __launch_bounds__(256)
proj_kernel(const float* __restrict__ A, const float* __restrict__ W,
            const float* __restrict__ bias,
            __nv_bfloat16* __restrict__ dsth, __nv_bfloat16* __restrict__ dstl)
{
    __shared__ float As[32*68];
    __shared__ float Bs[32*256];
    const int m0 = blockIdx.x * 64;
    const int tid = threadIdx.x;
    const int tx = tid & 31, ty = tid >> 5;

    u64 acc[4][8];
#pragma unroll
    for (int m = 0; m < 4; m++)
#pragma unroll
        for (int j = 0; j < 8; j++) acc[m][j] = 0;

    for (int k0 = 0; k0 < 256; k0 += 32) {
#pragma unroll
        for (int it = 0; it < 2; it++) {
            int fidx = tid + it * 256;
            int r = fidx >> 3, kv = (fidx & 7) * 4;
            float4 a = *(const float4*)&A[(m0 + r) * 256 + k0 + kv];
            As[(kv+0)*68 + r] = a.x; As[(kv+1)*68 + r] = a.y;
            As[(kv+2)*68 + r] = a.z; As[(kv+3)*68 + r] = a.w;
        }
#pragma unroll
        for (int it = 0; it < 8; it++) {
            int fidx = tid + it * 256;
            int kk = fidx >> 6, c4 = (fidx & 63) * 4;
            *(float4*)&Bs[kk*256 + c4] = *(const float4*)&W[(k0 + kk) * 256 + c4];
        }
        __syncthreads();
#pragma unroll 2
        for (int k = 0; k < 32; k++) {
            ulonglong2 q01 = *(const ulonglong2*)&As[k*68 + ty*8];
            ulonglong2 q23 = *(const ulonglong2*)&As[k*68 + ty*8 + 4];
            float4 b0 = *(const float4*)&Bs[k*256 + tx*8];
            float4 b1 = *(const float4*)&Bs[k*256 + tx*8 + 4];
            u64 qp[4] = {q01.x, q01.y, q23.x, q23.y};
            u64 bd[8] = {dup2(b0.x), dup2(b0.y), dup2(b0.z), dup2(b0.w),
                         dup2(b1.x), dup2(b1.y), dup2(b1.z), dup2(b1.w)};
#pragma unroll
            for (int m = 0; m < 4; m++)
#pragma unroll
                for (int j = 0; j < 8; j++)
                    fma2(acc[m][j], qp[m], bd[j]);
        }
        __syncthreads();
    }

    const int h = tx >> 3;
    const int d0 = (tx & 7) * 8;
#pragma unroll
    for (int m = 0; m < 4; m++) {
        float lo[8], hi[8];
#pragma unroll
        for (int j = 0; j < 8; j++) unpk(acc[m][j], lo[j], hi[j]);
#pragma unroll
        for (int e = 0; e < 2; e++) {
            int row = m0 + ty * 8 + 2*m + e;
            int b_  = row / LL;
            int l   = row - b_ * LL;
            float* src = e ? hi : lo;
            float o[8];
#pragma unroll
            for (int j = 0; j < 8; j++) {
                float vv = src[j];
                if (RELU) { vv += bias[d0 + j]; vv = vv > 0.f ? vv : 0.f; }
                o[j] = vv;
            }
            u32 hp[4], lp[4];
            split8(o, hp, lp);
            size_t base = ((size_t)(b_ * HH + h) * LP + l) * DK + d0;
            *(uint4*)(dsth + base) = make_uint4(hp[0], hp[1], hp[2], hp[3]);
            *(uint4*)(dstl + base) = make_uint4(lp[0], lp[1], lp[2], lp[3]);
        }
    }
}

// ===========================================================================
// K2: HMMA attention (bf16 3x-split), flash-style, P register-resident.
// grid (4 l-tiles of 128, 256 bh). 256 threads = 8 warps; warp w owns rows
// 16w..16w+15. j in 4 chunks of 128.
// ===========================================================================
#define SW2H 0
#define SW2L 18432
#define SVH  36864
#define SVL  55296
#define SB2  73728
#define ATTN_SMEM_BYTES 74240
#define TSTR 72     // bf16 row stride of smem tiles

__global__ void __launch_bounds__(256)
attn_kernel(const __nv_bfloat16* __restrict__ wh, const __nv_bfloat16* __restrict__ wl,
            const __nv_bfloat16* __restrict__ vhh, const __nv_bfloat16* __restrict__ vhl,
            const __nv_bfloat16* __restrict__ w2h, const __nv_bfloat16* __restrict__ w2l,
            const float* __restrict__ b2, float* __restrict__ O)
{
    extern __shared__ char smc[];
    const u32 smb = smem_u32(smc);
    float* b2f = (float*)(smc + SB2);

    const int tid  = threadIdx.x;
    const int w    = tid >> 5;
    const int lane = tid & 31;
    const int bh = blockIdx.y;
    const int b_ = bh >> 2, h = bh & 3;
    const int l0 = blockIdx.x * 128;

    // ---- A fragments: direct LDG from gmem (weight hi/lo), once ----
    const u32* awh = (const u32*)(wh + (size_t)bh * LP * DK);
    const u32* awl = (const u32*)(wl + (size_t)bh * LP * DK);
    const int arow = l0 + 16 * w + (lane >> 2);
    const int ac = lane & 3;
    u32 a_h[4][4], a_l[4][4];
#pragma unroll
    for (int ks = 0; ks < 4; ks++) {
        u32 i0 = (u32)(arow * 32 + ks * 8 + ac);
        a_h[ks][0] = awh[i0];           a_h[ks][1] = awh[i0 + 256];
        a_h[ks][2] = awh[i0 + 4];       a_h[ks][3] = awh[i0 + 260];
        a_l[ks][0] = awl[i0];           a_l[ks][1] = awl[i0 + 256];
        a_l[ks][2] = awl[i0 + 4];       a_l[ks][3] = awl[i0 + 260];
    }

    // ldmatrix per-lane address components
    const int r8 = lane & 7, ti = lane >> 3;
    const u32 w2row = (u32)(r8 + ((ti >> 1) << 3));   // S B-frags (non-trans)
    const u32 w2col = (u32)((ti & 1) << 3);
    const u32 vrow  = (u32)(r8 + ((ti & 1) << 3));    // PV B-frags (.trans)
    const u32 vcol  = (u32)((ti >> 1) << 3);

    float oacc[8][4];
#pragma unroll
    for (int i = 0; i < 8; i++)
#pragma unroll
        for (int j = 0; j < 4; j++) oacc[i][j] = 0.f;
    float lsum0 = 0.f, lsum1 = 0.f;

    const uint4* gw2h = (const uint4*)w2h;
    const uint4* gw2l = (const uint4*)w2l;
    const uint4* gvh  = (const uint4*)(vhh + (size_t)bh * LP * DK);
    const uint4* gvl  = (const uint4*)(vhl + (size_t)bh * LP * DK);

    for (int jt = 0; jt < 4; jt++) {
        const int j0 = jt * 128;
        __syncthreads();
        // fill smem tiles: W2 chunk [128 j][64 d], V chunk [128 j][64 c]
        {
            const int rbase = j0 * 8;     // uint4 index of chunk start
            for (int t = tid; t < 1024; t += 256) {
                int rr = t >> 3, qq = t & 7;
                u32 off = (u32)(rr * (TSTR*2) + qq * 16);
                *(uint4*)(smc + SW2H + off) = gw2h[rbase + t];
                *(uint4*)(smc + SW2L + off) = gw2l[rbase + t];
                *(uint4*)(smc + SVH  + off) = gvh [rbase + t];
                *(uint4*)(smc + SVL  + off) = gvl [rbase + t];
            }
            if (tid < 128) b2f[tid] = (j0 + tid < LL) ? b2[j0 + tid] : 0.f;
        }
        __syncthreads();

        // ---- S = A @ W2^T  (16 n-blocks of 8 cols) ----
        float sacc[16][4];
#pragma unroll
        for (int i = 0; i < 16; i++)
#pragma unroll
            for (int j = 0; j < 4; j++) sacc[i][j] = 0.f;

#pragma unroll
        for (int ks = 0; ks < 4; ks++) {
#pragma unroll
            for (int nbp = 0; nbp < 8; nbp++) {
                u32 addr_h = smb + SW2H +
                    ((u32)(nbp*16) + w2row) * (TSTR*2) + ((u32)(ks*16) + w2col) * 2;
                u32 addr_l = addr_h + (SW2L - SW2H);
                u32 bh4[4], bl4[4];
                ldsm4(bh4, addr_h);
                ldsm4(bl4, addr_l);
                mma_bf16(sacc[2*nbp],   a_h[ks], bh4[0], bh4[1]);
                mma_bf16(sacc[2*nbp],   a_h[ks], bl4[0], bl4[1]);
                mma_bf16(sacc[2*nbp],   a_l[ks], bh4[0], bh4[1]);
                mma_bf16(sacc[2*nbp+1], a_h[ks], bh4[2], bh4[3]);
                mma_bf16(sacc[2*nbp+1], a_h[ks], bl4[2], bl4[3]);
                mma_bf16(sacc[2*nbp+1], a_l[ks], bh4[2], bh4[3]);
            }
        }

        // ---- P = exp(S + b2) in-register; pack to PV A-frags ----
        u32 pa_h[8][4], pa_l[8][4];
#pragma unroll
        for (int nb = 0; nb < 16; nb++) {
            const int ks = nb >> 1, hb = (nb & 1) * 2;
            const int col0 = nb * 8 + 2 * ac;
            const bool valid = (j0 + col0) < LL;
            const float bb0 = b2f[col0], bb1 = b2f[col0 + 1];
            float p0 = valid ? __expf(sacc[nb][0] + bb0) : 0.f;
            float p1 = valid ? __expf(sacc[nb][1] + bb1) : 0.f;
            float p2 = valid ? __expf(sacc[nb][2] + bb0) : 0.f;
            float p3 = valid ? __expf(sacc[nb][3] + bb1) : 0.f;
            lsum0 += p0 + p1; lsum1 += p2 + p3;
            u32 h01 = packbf(p0, p1), h23 = packbf(p2, p3);
            pa_h[ks][hb]   = h01;
            pa_h[ks][hb+1] = h23;
            pa_l[ks][hb]   = packbf(p0 - bflo(h01), p1 - bfhi(h01));
            pa_l[ks][hb+1] = packbf(p2 - bflo(h23), p3 - bfhi(h23));
        }

        // ---- O += P @ V ----
#pragma unroll
        for (int ks = 0; ks < 8; ks++) {
#pragma unroll
            for (int nbp = 0; nbp < 4; nbp++) {
                u32 addr_h = smb + SVH +
                    ((u32)(ks*16) + vrow) * (TSTR*2) + ((u32)(nbp*16) + vcol) * 2;
                u32 addr_l = addr_h + (SVL - SVH);
                u32 vh4[4], vl4[4];
                ldsm4t(vh4, addr_h);
                ldsm4t(vl4, addr_l);
                mma_bf16(oacc[2*nbp],   pa_h[ks], vh4[0], vh4[1]);
                mma_bf16(oacc[2*nbp],   pa_h[ks], vl4[0], vl4[1]);
                mma_bf16(oacc[2*nbp],   pa_l[ks], vh4[0], vh4[1]);
                mma_bf16(oacc[2*nbp+1], pa_h[ks], vh4[2], vh4[3]);
                mma_bf16(oacc[2*nbp+1], pa_h[ks], vl4[2], vl4[3]);
                mma_bf16(oacc[2*nbp+1], pa_l[ks], vh4[2], vh4[3]);
            }
        }
    }

    // ---- epilogue: quad-reduce row sums, normalize, store ----
    lsum0 += __shfl_xor_sync(0xffffffffu, lsum0, 1);
    lsum0 += __shfl_xor_sync(0xffffffffu, lsum0, 2);
    lsum1 += __shfl_xor_sync(0xffffffffu, lsum1, 1);
    lsum1 += __shfl_xor_sync(0xffffffffu, lsum1, 2);
    const float inv0 = 1.f / lsum0, inv1 = 1.f / lsum1;

    const int r = lane >> 2;
    const int lA = l0 + 16 * w + r;
    const int lB = lA + 8;
#pragma unroll
    for (int cb = 0; cb < 8; cb++) {
        int col = h * 64 + cb * 8 + 2 * ac;
        if (lA < LL)
            *(float2*)&O[((size_t)(b_ * LL + lA)) * FF + col] =
                make_float2(oacc[cb][0] * inv0, oacc[cb][1] * inv0);
        if (lB < LL)
            *(float2*)&O[((size_t)(b_ * LL + lB)) * FF + col] =
                make_float2(oacc[cb][2] * inv1, oacc[cb][3] * inv1);
    }
}

// ===========================================================================
// K3: fused fc GEMM + residual + LayerNorm -> out (scalar f32x2)
// ===========================================================================
__global__ void __launch_bounds__(256)
fc_ln_kernel(const float* __restrict__ A, const float* __restrict__ W,
             const float* __restrict__ Res, const float* __restrict__ lng,
             const float* __restrict__ lnb, float* __restrict__ Out)
{
    __shared__ float As[32*68];
    __shared__ float Bs[32*256];
    const int m0 = blockIdx.x * 64;
    const int tid = threadIdx.x;
    const int tx = tid & 31, ty = tid >> 5;

    u64 acc[4][8];
#pragma unroll
    for (int m = 0; m < 4; m++)
#pragma unroll
        for (int j = 0; j < 8; j++) acc[m][j] = 0;

    for (int k0 = 0; k0 < 256; k0 += 32) {
#pragma unroll
        for (int it = 0; it < 2; it++) {
            int fidx = tid + it * 256;
            int r = fidx >> 3, kv = (fidx & 7) * 4;
            float4 a = *(const float4*)&A[(m0 + r) * 256 + k0 + kv];
            As[(kv+0)*68 + r] = a.x; As[(kv+1)*68 + r] = a.y;
            As[(kv+2)*68 + r] = a.z; As[(kv+3)*68 + r] = a.w;
        }
#pragma unroll
        for (int it = 0; it < 8; it++) {
            int fidx = tid + it * 256;
            int kk = fidx >> 6, c4 = (fidx & 63) * 4;
            *(float4*)&Bs[kk*256 + c4] = *(const float4*)&W[(k0 + kk) * 256 + c4];
        }
        __syncthreads();
#pragma unroll 2
        for (int k = 0; k < 32; k++) {
            ulonglong2 q01 = *(const ulonglong2*)&As[k*68 + ty*8];
            ulonglong2 q23 = *(const ulonglong2*)&As[k*68 + ty*8 + 4];
            float4 b0 = *(const float4*)&Bs[k*256 + tx*8];
            float4 b1 = *(const float4*)&Bs[k*256 + tx*8 + 4];
            u64 qp[4] = {q01.x, q01.y, q23.x, q23.y};
            u64 bd[8] = {dup2(b0.x), dup2(b0.y), dup2(b0.z), dup2(b0.w),
                         dup2(b1.x), dup2(b1.y), dup2(b1.z), dup2(b1.w)};
#pragma unroll
            for (int m = 0; m < 4; m++)
#pragma unroll
                for (int j = 0; j < 8; j++)
                    fma2(acc[m][j], qp[m], bd[j]);
        }
        __syncthreads();
    }

    float4 g0 = *(const float4*)&lng[tx*8];
    float4 g1 = *(const float4*)&lng[tx*8 + 4];
    float4 bb0 = *(const float4*)&lnb[tx*8];
    float4 bb1 = *(const float4*)&lnb[tx*8 + 4];
    float g[8]  = {g0.x, g0.y, g0.z, g0.w, g1.x, g1.y, g1.z, g1.w};
    float lb[8] = {bb0.x, bb0.y, bb0.z, bb0.w, bb1.x, bb1.y, bb1.z, bb1.w};

#pragma unroll
    for (int m = 0; m < 4; m++) {
        float lo[8], hi[8];
#pragma unroll
        for (int j = 0; j < 8; j++) unpk(acc[m][j], lo[j], hi[j]);
#pragma unroll
        for (int e = 0; e < 2; e++) {
            int row = m0 + ty * 8 + 2*m + e;
            const float* rp = &Res[(size_t)row * 256 + tx*8];
            float4 r0 = *(const float4*)&rp[0];
            float4 r1 = *(const float4*)&rp[4];
            float* src = e ? hi : lo;
            float v[8] = {src[0]+r0.x, src[1]+r0.y, src[2]+r0.z, src[3]+r0.w,
                          src[4]+r1.x, src[5]+r1.y, src[6]+r1.z, src[7]+r1.w};
            float s = 0.f;
#pragma unroll
            for (int j = 0; j < 8; j++) s += v[j];
#pragma unroll
            for (int o = 16; o; o >>= 1) s += __shfl_xor_sync(0xffffffffu, s, o);
            float mu = s * (1.f / 256.f);
            float vs = 0.f;
#pragma unroll
            for (int j = 0; j < 8; j++) { float d = v[j] - mu; vs += d * d; }
#pragma unroll
            for (int o = 16; o; o >>= 1) vs += __shfl_xor_sync(0xffffffffu, vs, o);
            float rstd = rsqrtf(vs * (1.f / 256.f) + 1e-6f);
            float o8[8];
#pragma unroll
            for (int j = 0; j < 8; j++) o8[j] = (v[j] - mu) * rstd * g[j] + lb[j];
            float* op = &Out[(size_t)row * 256 + tx*8];
            *(float4*)&op[0] = make_float4(o8[0], o8[1], o8[2], o8[3]);
            *(float4*)&op[4] = make_float4(o8[4], o8[5], o8[6], o8[7]);
        }
    }
}

// ===========================================================================
// launch
// ===========================================================================
extern "C" void kernel_launch(void* const* d_in, const int* in_sizes, int n_in,
                              void* d_out, int out_size)
{
    const float* q    = (const float*)d_in[0];
    const float* v    = (const float*)d_in[2];
    const float* w_qs = (const float*)d_in[3];
    const float* w_vs = (const float*)d_in[4];
    const float* w1   = (const float*)d_in[5];
    const float* b1   = (const float*)d_in[6];
    const float* w2   = (const float*)d_in[7];
    const float* b2   = (const float*)d_in[8];
    const float* fc_w = (const float*)d_in[9];
    const float* ln_g = (const float*)d_in[10];
    const float* ln_b = (const float*)d_in[11];
    float* out = (float*)d_out;

    __nv_bfloat16 *wh, *wl, *vhh, *vhl, *w2h, *w2l;
    float *o, *wc;
    cudaGetSymbolAddress((void**)&wh,  g_wh);
    cudaGetSymbolAddress((void**)&wl,  g_wl);
    cudaGetSymbolAddress((void**)&vhh, g_vhh);
    cudaGetSymbolAddress((void**)&vhl, g_vhl);
    cudaGetSymbolAddress((void**)&w2h, g_w2h);
    cudaGetSymbolAddress((void**)&w2l, g_w2l);
    cudaGetSymbolAddress((void**)&o,   g_o);
    cudaGetSymbolAddress((void**)&wc,  g_wc);

    cudaFuncSetAttribute(attn_kernel, cudaFuncAttributeMaxDynamicSharedMemorySize,
                         ATTN_SMEM_BYTES);

    wcomb_kernel<<<64, 256>>>(w_qs, w1, wc);
    w2prep_kernel<<<128, 256>>>(w2, w2h, w2l);

    proj_kernel<true ><<<BL / 64, 256>>>(q, wc,   b1, wh,  wl);
    proj_kernel<false><<<BL / 64, 256>>>(v, w_vs, b1, vhh, vhl);

    dim3 gAttn(4, BB * HH);
    attn_kernel<<<gAttn, 256, ATTN_SMEM_BYTES>>>(wh, wl, vhh, vhl, w2h, w2l, b2, o);

    fc_ln_kernel<<<BL / 64, 256>>>(o, fc_w, q, ln_g, ln_b, out);
}

// round 12
// speedup vs baseline: 1.9837x; 1.2611x over previous
#include <cuda_runtime.h>
#include <cuda_bf16.h>
#include <math.h>

#define BB 64
#define LL 500
#define FF 256
#define HH 4
#define DK 64
#define BL (BB*LL)      // 32000
#define LP 512          // padded seq len

typedef unsigned long long u64;
typedef unsigned int u32;

// ---------------- bf16 pack/split helpers ----------------
__device__ __forceinline__ u32 packbf(float f0, float f1) {
    u32 d; asm("cvt.rn.bf16x2.f32 %0, %1, %2;" : "=r"(d) : "f"(f1), "f"(f0));
    return d;   // low half = f0
}
__device__ __forceinline__ float bflo(u32 d) { return __uint_as_float(d << 16); }
__device__ __forceinline__ float bfhi(u32 d) { return __uint_as_float(d & 0xffff0000u); }

// ---------------- HMMA helpers ----------------
__device__ __forceinline__ void mma_bf16(float* d, const u32* a, u32 b0, u32 b1) {
    asm volatile(
        "mma.sync.aligned.m16n8k16.row.col.f32.bf16.bf16.f32 "
        "{%0,%1,%2,%3}, {%4,%5,%6,%7}, {%8,%9}, {%0,%1,%2,%3};"
        : "+f"(d[0]), "+f"(d[1]), "+f"(d[2]), "+f"(d[3])
        : "r"(a[0]), "r"(a[1]), "r"(a[2]), "r"(a[3]), "r"(b0), "r"(b1));
}
__device__ __forceinline__ void ldsm4(u32* r, u32 addr) {
    asm volatile("ldmatrix.sync.aligned.m8n8.x4.shared.b16 {%0,%1,%2,%3}, [%4];"
        : "=r"(r[0]), "=r"(r[1]), "=r"(r[2]), "=r"(r[3]) : "r"(addr));
}
__device__ __forceinline__ void ldsm4t(u32* r, u32 addr) {
    asm volatile("ldmatrix.sync.aligned.m8n8.x4.trans.shared.b16 {%0,%1,%2,%3}, [%4];"
        : "=r"(r[0]), "=r"(r[1]), "=r"(r[2]), "=r"(r[3]) : "r"(addr));
}
__device__ __forceinline__ u32 smem_u32(const void* p) {
    u32 a;
    asm("{ .reg .u64 t; cvta.to.shared.u64 t, %1; cvt.u32.u64 %0, t; }"
        : "=r"(a) : "l"(p));
    return a;
}

// ---------------- scratch ----------------
__device__ __nv_bfloat16 g_wh  [BB*HH*LP*DK];  // weight hi, [bh][512][64]
__device__ __nv_bfloat16 g_wl  [BB*HH*LP*DK];  // weight lo
__device__ __nv_bfloat16 g_vhh [BB*HH*LP*DK];  // vh hi
__device__ __nv_bfloat16 g_vhl [BB*HH*LP*DK];  // vh lo
__device__ __nv_bfloat16 g_w2h [LP*DK];        // w2^T hi, [j 512][d 64]
__device__ __nv_bfloat16 g_w2l [LP*DK];        // w2^T lo
__device__ float         g_o   [BB*LL*FF];     // attention out, [B,L,F]
__device__ __nv_bfloat16 g_wcth[FF*FF];        // Wcomb^T hi, [n][k]
__device__ __nv_bfloat16 g_wctl[FF*FF];
__device__ __nv_bfloat16 g_vsth[FF*FF];        // w_vs^T hi
__device__ __nv_bfloat16 g_vstl[FF*FF];
__device__ __nv_bfloat16 g_fcth[FF*FF];        // fc_w^T hi
__device__ __nv_bfloat16 g_fctl[FF*FF];

// ===========================================================================
// K0: Wcomb = w_qs . blockdiag(w1), written TRANSPOSED + bf16 split: [n][k]
// ===========================================================================
__global__ void __launch_bounds__(256)
wcomb_kernel(const float* __restrict__ wqs, const float* __restrict__ w1,
             __nv_bfloat16* __restrict__ th, __nv_bfloat16* __restrict__ tl)
{
    __shared__ float w1s[64*64];
    const int tid = threadIdx.x;
    for (int i = tid; i < 4096; i += 256) w1s[i] = w1[i];
    __syncthreads();
    const int d = tid & 63, sub = tid >> 6;
    const int f = blockIdx.x * 4 + sub;
#pragma unroll
    for (int h = 0; h < 4; h++) {
        float acc = 0.f;
        const float* wr = &wqs[f*256 + h*64];
#pragma unroll 8
        for (int e = 0; e < 64; e++)
            acc = fmaf(wr[e], w1s[e*64 + d], acc);
        int n = h * 64 + d;
        __nv_bfloat16 hb = __float2bfloat16(acc);
        th[n*256 + f] = hb;
        tl[n*256 + f] = __float2bfloat16(acc - __bfloat162float(hb));
    }
}

// ===========================================================================
// K0b: generic transpose + split: out[n][k] = split(W[k][n]),  256x256
// ===========================================================================
__global__ void __launch_bounds__(256)
tsplit_kernel(const float* __restrict__ W,
              __nv_bfloat16* __restrict__ th, __nv_bfloat16* __restrict__ tl)
{
    const int n = blockIdx.x, k = threadIdx.x;
    float x = W[k*256 + n];
    __nv_bfloat16 hb = __float2bfloat16(x);
    th[n*256 + k] = hb;
    tl[n*256 + k] = __float2bfloat16(x - __bfloat162float(hb));
}

// ===========================================================================
// K0c: w2 transpose + bf16 split:  [j 512][d 64], j>=500 -> 0
// ===========================================================================
__global__ void __launch_bounds__(256)
w2prep_kernel(const float* __restrict__ w2,
              __nv_bfloat16* __restrict__ dh, __nv_bfloat16* __restrict__ dl)
{
    int idx = blockIdx.x * 256 + threadIdx.x;   // 512*64 total
    int j = idx >> 6, d = idx & 63;
    float x = (j < LL) ? w2[d * LL + j] : 0.f;
    __nv_bfloat16 hb = __float2bfloat16(x);
    dh[idx] = hb;
    dl[idx] = __float2bfloat16(x - __bfloat162float(hb));
}

// ===========================================================================
// K1: HMMA projection GEMM  C = op(A @ W), bf16 3x-split, out [bh][512][64]
// CTA: 128 rows x 128 cols (grid 250 x 2). 8 warps: warp w = rows 16w, all cols.
// A fp32 split in-kernel; W^T pre-split. k-chunks of 32.
// ===========================================================================
#define ASTR 40   // bf16 row stride (80B): 8 rows cover all 32 banks

template<bool RELU>
__global__ void __launch_bounds__(256)
projh_kernel(const float* __restrict__ A,
             const __nv_bfloat16* __restrict__ WTh, const __nv_bfloat16* __restrict__ WTl,
             const float* __restrict__ bias,
             __nv_bfloat16* __restrict__ dsth, __nv_bfloat16* __restrict__ dstl)
{
    __shared__ __nv_bfloat16 Ah[128*ASTR], Al[128*ASTR];
    __shared__ __nv_bfloat16 Bh[128*ASTR], Bl[128*ASTR];
    __shared__ float biass[64];

    const int m0 = blockIdx.x * 128;
    const int n0 = blockIdx.y * 128;
    const int tid = threadIdx.x;
    const int w = tid >> 5, lane = tid & 31;
    const u32 sAh = smem_u32(Ah), sAl = smem_u32(Al);
    const u32 sBh = smem_u32(Bh), sBl = smem_u32(Bl);

    if (RELU && tid < 64) biass[tid] = bias[tid];

    // ldmatrix lane address components
    const int r8 = lane & 7, ti = lane >> 3;
    const int arow = r8 + ((ti & 1) << 3), acol = (ti >> 1) << 3;   // A frags
    const int brow = r8 + ((ti >> 1) << 3), bcol = (ti & 1) << 3;   // B frags

    float acc[16][4];
#pragma unroll
    for (int i = 0; i < 16; i++)
#pragma unroll
        for (int j = 0; j < 4; j++) acc[i][j] = 0.f;

    for (int kc = 0; kc < 8; kc++) {
        const int k0 = kc * 32;
        __syncthreads();
        // ---- A tile: 128r x 32k fp32 -> bf16 hi/lo ----
        {
            const int r = tid >> 1, hf = (tid & 1) * 16;
            const float* src = &A[(size_t)(m0 + r) * 256 + k0 + hf];
            float f[16];
            *(float4*)&f[0]  = *(const float4*)&src[0];
            *(float4*)&f[4]  = *(const float4*)&src[4];
            *(float4*)&f[8]  = *(const float4*)&src[8];
            *(float4*)&f[12] = *(const float4*)&src[12];
            u32 hp[8], lp[8];
#pragma unroll
            for (int i = 0; i < 8; i++) {
                hp[i] = packbf(f[2*i], f[2*i+1]);
                lp[i] = packbf(f[2*i] - bflo(hp[i]), f[2*i+1] - bfhi(hp[i]));
            }
            char* ah = (char*)Ah + r * 80 + hf * 2;
            char* al = (char*)Al + r * 80 + hf * 2;
            *(uint4*)ah        = make_uint4(hp[0], hp[1], hp[2], hp[3]);
            *(uint4*)(ah + 16) = make_uint4(hp[4], hp[5], hp[6], hp[7]);
            *(uint4*)al        = make_uint4(lp[0], lp[1], lp[2], lp[3]);
            *(uint4*)(al + 16) = make_uint4(lp[4], lp[5], lp[6], lp[7]);
        }
        // ---- B tile: 128n x 32k, plain copies of pre-split W^T ----
#pragma unroll
        for (int it = 0; it < 2; it++) {
            int idx = tid + it * 256;                 // 512 uint4
            int r = idx >> 2, qq = idx & 3;
            *(uint4*)((char*)Bh + r * 80 + qq * 16) =
                *(const uint4*)&WTh[(size_t)(n0 + r) * 256 + k0 + qq * 8];
            *(uint4*)((char*)Bl + r * 80 + qq * 16) =
                *(const uint4*)&WTl[(size_t)(n0 + r) * 256 + k0 + qq * 8];
        }
        __syncthreads();

#pragma unroll
        for (int ks = 0; ks < 2; ks++) {
            u32 a_h[4], a_l[4];
            const u32 aoff = (u32)((16*w + arow) * 80 + (ks*16 + acol) * 2);
            ldsm4(a_h, sAh + aoff);
            ldsm4(a_l, sAl + aoff);
#pragma unroll
            for (int np = 0; np < 8; np++) {
                u32 b_h[4], b_l[4];
                const u32 boff = (u32)((np*16 + brow) * 80 + (ks*16 + bcol) * 2);
                ldsm4(b_h, sBh + boff);
                ldsm4(b_l, sBl + boff);
                mma_bf16(acc[2*np],   a_h, b_h[0], b_h[1]);
                mma_bf16(acc[2*np],   a_h, b_l[0], b_l[1]);
                mma_bf16(acc[2*np],   a_l, b_h[0], b_h[1]);
                mma_bf16(acc[2*np+1], a_h, b_h[2], b_h[3]);
                mma_bf16(acc[2*np+1], a_h, b_l[2], b_l[3]);
                mma_bf16(acc[2*np+1], a_l, b_h[2], b_h[3]);
            }
        }
    }

    // ---- epilogue: bias/relu, split to bf16 hi/lo, permute to [bh][512][64] ----
    const int r0 = lane >> 2, ac = lane & 3;
#pragma unroll
    for (int e = 0; e < 2; e++) {
        const int row = m0 + 16*w + r0 + 8*e;
        const int b_ = row / LL;
        const int l  = row - b_ * LL;
#pragma unroll
        for (int nb = 0; nb < 16; nb++) {
            const int n = n0 + nb * 8 + 2 * ac;
            float v0 = acc[nb][2*e], v1 = acc[nb][2*e+1];
            if (RELU) {
                v0 += biass[n & 63]; v0 = v0 > 0.f ? v0 : 0.f;
                v1 += biass[(n & 63) + 1]; v1 = v1 > 0.f ? v1 : 0.f;
            }
            u32 hp = packbf(v0, v1);
            u32 lp = packbf(v0 - bflo(hp), v1 - bfhi(hp));
            size_t base = ((size_t)(b_ * HH + (n >> 6)) * LP + l) * DK + (n & 63);
            *(u32*)&dsth[base] = hp;
            *(u32*)&dstl[base] = lp;
        }
    }
}

// ===========================================================================
// K2: HMMA attention (bf16 3x-split), flash-style, P register-resident.
// grid (4 l-tiles of 128, 256 bh). 8 warps; warp w rows 16w..16w+15.
// ===========================================================================
#define SW2H 0
#define SW2L 18432
#define SVH  36864
#define SVL  55296
#define SB2  73728
#define ATTN_SMEM_BYTES 74240
#define TSTR 72

__global__ void __launch_bounds__(256)
attn_kernel(const __nv_bfloat16* __restrict__ wh, const __nv_bfloat16* __restrict__ wl,
            const __nv_bfloat16* __restrict__ vhh, const __nv_bfloat16* __restrict__ vhl,
            const __nv_bfloat16* __restrict__ w2h, const __nv_bfloat16* __restrict__ w2l,
            const float* __restrict__ b2, float* __restrict__ O)
{
    extern __shared__ char smc[];
    const u32 smb = smem_u32(smc);
    float* b2f = (float*)(smc + SB2);

    const int tid  = threadIdx.x;
    const int w    = tid >> 5;
    const int lane = tid & 31;
    const int bh = blockIdx.y;
    const int b_ = bh >> 2, h = bh & 3;
    const int l0 = blockIdx.x * 128;

    const u32* awh = (const u32*)(wh + (size_t)bh * LP * DK);
    const u32* awl = (const u32*)(wl + (size_t)bh * LP * DK);
    const int arow = l0 + 16 * w + (lane >> 2);
    const int ac = lane & 3;
    u32 a_h[4][4], a_l[4][4];
#pragma unroll
    for (int ks = 0; ks < 4; ks++) {
        u32 i0 = (u32)(arow * 32 + ks * 8 + ac);
        a_h[ks][0] = awh[i0];           a_h[ks][1] = awh[i0 + 256];
        a_h[ks][2] = awh[i0 + 4];       a_h[ks][3] = awh[i0 + 260];
        a_l[ks][0] = awl[i0];           a_l[ks][1] = awl[i0 + 256];
        a_l[ks][2] = awl[i0 + 4];       a_l[ks][3] = awl[i0 + 260];
    }

    const int r8 = lane & 7, ti = lane >> 3;
    const u32 w2row = (u32)(r8 + ((ti >> 1) << 3));
    const u32 w2col = (u32)((ti & 1) << 3);
    const u32 vrow  = (u32)(r8 + ((ti & 1) << 3));
    const u32 vcol  = (u32)((ti >> 1) << 3);

    float oacc[8][4];
#pragma unroll
    for (int i = 0; i < 8; i++)
#pragma unroll
        for (int j = 0; j < 4; j++) oacc[i][j] = 0.f;
    float lsum0 = 0.f, lsum1 = 0.f;

    const uint4* gw2h = (const uint4*)w2h;
    const uint4* gw2l = (const uint4*)w2l;
    const uint4* gvh  = (const uint4*)(vhh + (size_t)bh * LP * DK);
    const uint4* gvl  = (const uint4*)(vhl + (size_t)bh * LP * DK);

    for (int jt = 0; jt < 4; jt++) {
        const int j0 = jt * 128;
        __syncthreads();
        {
            const int rbase = j0 * 8;
            for (int t = tid; t < 1024; t += 256) {
                int rr = t >> 3, qq = t & 7;
                u32 off = (u32)(rr * (TSTR*2) + qq * 16);
                *(uint4*)(smc + SW2H + off) = gw2h[rbase + t];
                *(uint4*)(smc + SW2L + off) = gw2l[rbase + t];
                *(uint4*)(smc + SVH  + off) = gvh [rbase + t];
                *(uint4*)(smc + SVL  + off) = gvl [rbase + t];
            }
            if (tid < 128) b2f[tid] = (j0 + tid < LL) ? b2[j0 + tid] : 0.f;
        }
        __syncthreads();

        float sacc[16][4];
#pragma unroll
        for (int i = 0; i < 16; i++)
#pragma unroll
            for (int j = 0; j < 4; j++) sacc[i][j] = 0.f;

#pragma unroll
        for (int ks = 0; ks < 4; ks++) {
#pragma unroll
            for (int nbp = 0; nbp < 8; nbp++) {
                u32 addr_h = smb + SW2H +
                    ((u32)(nbp*16) + w2row) * (TSTR*2) + ((u32)(ks*16) + w2col) * 2;
                u32 addr_l = addr_h + (SW2L - SW2H);
                u32 bh4[4], bl4[4];
                ldsm4(bh4, addr_h);
                ldsm4(bl4, addr_l);
                mma_bf16(sacc[2*nbp],   a_h[ks], bh4[0], bh4[1]);
                mma_bf16(sacc[2*nbp],   a_h[ks], bl4[0], bl4[1]);
                mma_bf16(sacc[2*nbp],   a_l[ks], bh4[0], bh4[1]);
                mma_bf16(sacc[2*nbp+1], a_h[ks], bh4[2], bh4[3]);
                mma_bf16(sacc[2*nbp+1], a_h[ks], bl4[2], bl4[3]);
                mma_bf16(sacc[2*nbp+1], a_l[ks], bh4[2], bh4[3]);
            }
        }

        u32 pa_h[8][4], pa_l[8][4];
#pragma unroll
        for (int nb = 0; nb < 16; nb++) {
            const int ks = nb >> 1, hb = (nb & 1) * 2;
            const int col0 = nb * 8 + 2 * ac;
            const bool valid = (j0 + col0) < LL;
            const float bb0 = b2f[col0], bb1 = b2f[col0 + 1];
            float p0 = valid ? __expf(sacc[nb][0] + bb0) : 0.f;
            float p1 = valid ? __expf(sacc[nb][1] + bb1) : 0.f;
            float p2 = valid ? __expf(sacc[nb][2] + bb0) : 0.f;
            float p3 = valid ? __expf(sacc[nb][3] + bb1) : 0.f;
            lsum0 += p0 + p1; lsum1 += p2 + p3;
            u32 h01 = packbf(p0, p1), h23 = packbf(p2, p3);
            pa_h[ks][hb]   = h01;
            pa_h[ks][hb+1] = h23;
            pa_l[ks][hb]   = packbf(p0 - bflo(h01), p1 - bfhi(h01));
            pa_l[ks][hb+1] = packbf(p2 - bflo(h23), p3 - bfhi(h23));
        }

#pragma unroll
        for (int ks = 0; ks < 8; ks++) {
#pragma unroll
            for (int nbp = 0; nbp < 4; nbp++) {
                u32 addr_h = smb + SVH +
                    ((u32)(ks*16) + vrow) * (TSTR*2) + ((u32)(nbp*16) + vcol) * 2;
                u32 addr_l = addr_h + (SVL - SVH);
                u32 vh4[4], vl4[4];
                ldsm4t(vh4, addr_h);
                ldsm4t(vl4, addr_l);
                mma_bf16(oacc[2*nbp],   pa_h[ks], vh4[0], vh4[1]);
                mma_bf16(oacc[2*nbp],   pa_h[ks], vl4[0], vl4[1]);
                mma_bf16(oacc[2*nbp],   pa_l[ks], vh4[0], vh4[1]);
                mma_bf16(oacc[2*nbp+1], pa_h[ks], vh4[2], vh4[3]);
                mma_bf16(oacc[2*nbp+1], pa_h[ks], vl4[2], vl4[3]);
                mma_bf16(oacc[2*nbp+1], pa_l[ks], vh4[2], vh4[3]);
            }
        }
    }

    lsum0 += __shfl_xor_sync(0xffffffffu, lsum0, 1);
    lsum0 += __shfl_xor_sync(0xffffffffu, lsum0, 2);
    lsum1 += __shfl_xor_sync(0xffffffffu, lsum1, 1);
    lsum1 += __shfl_xor_sync(0xffffffffu, lsum1, 2);
    const float inv0 = 1.f / lsum0, inv1 = 1.f / lsum1;

    const int r = lane >> 2;
    const int lA = l0 + 16 * w + r;
    const int lB = lA + 8;
#pragma unroll
    for (int cb = 0; cb < 8; cb++) {
        int col = h * 64 + cb * 8 + 2 * ac;
        if (lA < LL)
            *(float2*)&O[((size_t)(b_ * LL + lA)) * FF + col] =
                make_float2(oacc[cb][0] * inv0, oacc[cb][1] * inv0);
        if (lB < LL)
            *(float2*)&O[((size_t)(b_ * LL + lB)) * FF + col] =
                make_float2(oacc[cb][2] * inv1, oacc[cb][3] * inv1);
    }
}

// ===========================================================================
// K3: HMMA fc GEMM + residual + LayerNorm.
// CTA 64 rows x 256 cols (full width -> LN in-CTA). 8 warps: wr=w&3 rows 16wr,
// cg=w>>2 col half. grid 500.
// ===========================================================================
#define FC_BH   0
#define FC_BL   20480
#define FC_AH   40960
#define FC_AL   46080
#define FC_PS   51200
#define FC_PQ   51712
#define FC_SG   52224
#define FC_SB   53248
#define FC_SMEM_BYTES 54272

__global__ void __launch_bounds__(256)
fcln_kernel(const float* __restrict__ A,
            const __nv_bfloat16* __restrict__ WTh, const __nv_bfloat16* __restrict__ WTl,
            const float* __restrict__ Res, const float* __restrict__ lng,
            const float* __restrict__ lnb, float* __restrict__ Out)
{
    extern __shared__ char smc[];
    const u32 sBh = smem_u32(smc) + FC_BH, sBl = smem_u32(smc) + FC_BL;
    const u32 sAh = smem_u32(smc) + FC_AH, sAl = smem_u32(smc) + FC_AL;
    float* ps = (float*)(smc + FC_PS);   // [2][64] partial sums
    float* pq = (float*)(smc + FC_PQ);   // [2][64] partial sumsq
    float* sg = (float*)(smc + FC_SG);
    float* sb = (float*)(smc + FC_SB);

    const int m0 = blockIdx.x * 64;
    const int tid = threadIdx.x;
    const int w = tid >> 5, lane = tid & 31;
    const int wr = w & 3, cg = w >> 2;

    if (tid < 256) { sg[tid] = lng[tid]; sb[tid] = lnb[tid]; }

    const int r8 = lane & 7, ti = lane >> 3;
    const int arow = r8 + ((ti & 1) << 3), acol = (ti >> 1) << 3;
    const int brow = r8 + ((ti >> 1) << 3), bcol = (ti & 1) << 3;

    float acc[16][4];
#pragma unroll
    for (int i = 0; i < 16; i++)
#pragma unroll
        for (int j = 0; j < 4; j++) acc[i][j] = 0.f;

    for (int kc = 0; kc < 8; kc++) {
        const int k0 = kc * 32;
        __syncthreads();
        // A tile: 64r x 32k fp32 -> split
        {
            const int r = tid >> 2, q = (tid & 3) * 8;
            const float* src = &A[(size_t)(m0 + r) * 256 + k0 + q];
            float f[8];
            *(float4*)&f[0] = *(const float4*)&src[0];
            *(float4*)&f[4] = *(const float4*)&src[4];
            u32 hp[4], lp[4];
#pragma unroll
            for (int i = 0; i < 4; i++) {
                hp[i] = packbf(f[2*i], f[2*i+1]);
                lp[i] = packbf(f[2*i] - bflo(hp[i]), f[2*i+1] - bfhi(hp[i]));
            }
            *(uint4*)(smc + FC_AH + r * 80 + q * 2) = make_uint4(hp[0], hp[1], hp[2], hp[3]);
            *(uint4*)(smc + FC_AL + r * 80 + q * 2) = make_uint4(lp[0], lp[1], lp[2], lp[3]);
        }
        // B tile: 256n x 32k copies
#pragma unroll
        for (int it = 0; it < 4; it++) {
            int idx = tid + it * 256;                 // 1024 uint4
            int r = idx >> 2, qq = idx & 3;
            *(uint4*)(smc + FC_BH + r * 80 + qq * 16) =
                *(const uint4*)&WTh[(size_t)r * 256 + k0 + qq * 8];
            *(uint4*)(smc + FC_BL + r * 80 + qq * 16) =
                *(const uint4*)&WTl[(size_t)r * 256 + k0 + qq * 8];
        }
        __syncthreads();

#pragma unroll
        for (int ks = 0; ks < 2; ks++) {
            u32 a_h[4], a_l[4];
            const u32 aoff = (u32)((16*wr + arow) * 80 + (ks*16 + acol) * 2);
            ldsm4(a_h, sAh + aoff);
            ldsm4(a_l, sAl + aoff);
#pragma unroll
            for (int np = 0; np < 8; np++) {
                u32 b_h[4], b_l[4];
                const u32 boff = (u32)((cg*128 + np*16 + brow) * 80 + (ks*16 + bcol) * 2);
                ldsm4(b_h, sBh + boff);
                ldsm4(b_l, sBl + boff);
                mma_bf16(acc[2*np],   a_h, b_h[0], b_h[1]);
                mma_bf16(acc[2*np],   a_h, b_l[0], b_l[1]);
                mma_bf16(acc[2*np],   a_l, b_h[0], b_h[1]);
                mma_bf16(acc[2*np+1], a_h, b_h[2], b_h[3]);
                mma_bf16(acc[2*np+1], a_h, b_l[2], b_l[3]);
                mma_bf16(acc[2*np+1], a_l, b_h[2], b_h[3]);
            }
        }
    }

    // ---- epilogue: += residual, LN stats (E[x^2]-mu^2), normalize, store ----
    const int r0 = lane >> 2, ac = lane & 3;
    float s[2] = {0.f, 0.f}, q2[2] = {0.f, 0.f};
#pragma unroll
    for (int e = 0; e < 2; e++) {
        const int row = m0 + 16*wr + r0 + 8*e;
#pragma unroll
        for (int nb = 0; nb < 16; nb++) {
            const int col = cg*128 + nb*8 + 2*ac;
            float2 rv = *(const float2*)&Res[(size_t)row * 256 + col];
            acc[nb][2*e]   += rv.x;
            acc[nb][2*e+1] += rv.y;
            s[e]  += acc[nb][2*e] + acc[nb][2*e+1];
            q2[e] += acc[nb][2*e]*acc[nb][2*e] + acc[nb][2*e+1]*acc[nb][2*e+1];
        }
    }
#pragma unroll
    for (int e = 0; e < 2; e++) {
        s[e]  += __shfl_xor_sync(0xffffffffu, s[e], 1);
        s[e]  += __shfl_xor_sync(0xffffffffu, s[e], 2);
        q2[e] += __shfl_xor_sync(0xffffffffu, q2[e], 1);
        q2[e] += __shfl_xor_sync(0xffffffffu, q2[e], 2);
    }
    __syncthreads();   // protect smem reuse ordering (ps/pq fresh per CTA)
    if (ac == 0) {
#pragma unroll
        for (int e = 0; e < 2; e++) {
            int rl = 16*wr + r0 + 8*e;
            ps[cg*64 + rl] = s[e];
            pq[cg*64 + rl] = q2[e];
        }
    }
    __syncthreads();
#pragma unroll
    for (int e = 0; e < 2; e++) {
        const int rl = 16*wr + r0 + 8*e;
        const int row = m0 + rl;
        const float sum = ps[rl] + ps[64 + rl];
        const float sq  = pq[rl] + pq[64 + rl];
        const float mu = sum * (1.f / 256.f);
        float var = sq * (1.f / 256.f) - mu * mu;
        var = var > 0.f ? var : 0.f;
        const float rstd = rsqrtf(var + 1e-6f);
#pragma unroll
        for (int nb = 0; nb < 16; nb++) {
            const int col = cg*128 + nb*8 + 2*ac;
            float o0 = (acc[nb][2*e]   - mu) * rstd * sg[col]     + sb[col];
            float o1 = (acc[nb][2*e+1] - mu) * rstd * sg[col + 1] + sb[col + 1];
            *(float2*)&Out[(size_t)row * 256 + col] = make_float2(o0, o1);
        }
    }
}

// ===========================================================================
// launch
// ===========================================================================
extern "C" void kernel_launch(void* const* d_in, const int* in_sizes, int n_in,
                              void* d_out, int out_size)
{
    const float* q    = (const float*)d_in[0];
    const float* v    = (const float*)d_in[2];
    const float* w_qs = (const float*)d_in[3];
    const float* w_vs = (const float*)d_in[4];
    const float* w1   = (const float*)d_in[5];
    const float* b1   = (const float*)d_in[6];
    const float* w2   = (const float*)d_in[7];
    const float* b2   = (const float*)d_in[8];
    const float* fc_w = (const float*)d_in[9];
    const float* ln_g = (const float*)d_in[10];
    const float* ln_b = (const float*)d_in[11];
    float* out = (float*)d_out;

    __nv_bfloat16 *wh, *wl, *vhh, *vhl, *w2h, *w2l;
    __nv_bfloat16 *wcth, *wctl, *vsth, *vstl, *fcth, *fctl;
    float *o;
    cudaGetSymbolAddress((void**)&wh,   g_wh);
    cudaGetSymbolAddress((void**)&wl,   g_wl);
    cudaGetSymbolAddress((void**)&vhh,  g_vhh);
    cudaGetSymbolAddress((void**)&vhl,  g_vhl);
    cudaGetSymbolAddress((void**)&w2h,  g_w2h);
    cudaGetSymbolAddress((void**)&w2l,  g_w2l);
    cudaGetSymbolAddress((void**)&o,    g_o);
    cudaGetSymbolAddress((void**)&wcth, g_wcth);
    cudaGetSymbolAddress((void**)&wctl, g_wctl);
    cudaGetSymbolAddress((void**)&vsth, g_vsth);
    cudaGetSymbolAddress((void**)&vstl, g_vstl);
    cudaGetSymbolAddress((void**)&fcth, g_fcth);
    cudaGetSymbolAddress((void**)&fctl, g_fctl);

    cudaFuncSetAttribute(attn_kernel, cudaFuncAttributeMaxDynamicSharedMemorySize,
                         ATTN_SMEM_BYTES);
    cudaFuncSetAttribute(fcln_kernel, cudaFuncAttributeMaxDynamicSharedMemorySize,
                         FC_SMEM_BYTES);

    wcomb_kernel<<<64, 256>>>(w_qs, w1, wcth, wctl);
    tsplit_kernel<<<256, 256>>>(w_vs, vsth, vstl);
    tsplit_kernel<<<256, 256>>>(fc_w, fcth, fctl);
    w2prep_kernel<<<128, 256>>>(w2, w2h, w2l);

    dim3 gProj(250, 2);
    projh_kernel<true ><<<gProj, 256>>>(q, wcth, wctl, b1, wh,  wl);
    projh_kernel<false><<<gProj, 256>>>(v, vsth, vstl, b1, vhh, vhl);

    dim3 gAttn(4, BB * HH);
    attn_kernel<<<gAttn, 256, ATTN_SMEM_BYTES>>>(wh, wl, vhh, vhl, w2h, w2l, b2, o);

    fcln_kernel<<<500, 256, FC_SMEM_BYTES>>>(o, fcth, fctl, q, ln_g, ln_b, out);
}

// round 15
// speedup vs baseline: 2.2050x; 1.1116x over previous
#include <cuda_runtime.h>
#include <cuda_bf16.h>
#include <math.h>

#define BB 64
#define LL 500
#define FF 256
#define HH 4
#define DK 64
#define BL (BB*LL)      // 32000
#define LP 512          // padded seq len

typedef unsigned long long u64;
typedef unsigned int u32;

// ---------------- bf16 pack/split helpers ----------------
__device__ __forceinline__ u32 packbf(float f0, float f1) {
    u32 d; asm("cvt.rn.bf16x2.f32 %0, %1, %2;" : "=r"(d) : "f"(f1), "f"(f0));
    return d;   // low half = f0
}
__device__ __forceinline__ float bflo(u32 d) { return __uint_as_float(d << 16); }
__device__ __forceinline__ float bfhi(u32 d) { return __uint_as_float(d & 0xffff0000u); }

// ---------------- HMMA / cp.async helpers ----------------
__device__ __forceinline__ void mma_bf16(float* d, const u32* a, u32 b0, u32 b1) {
    asm volatile(
        "mma.sync.aligned.m16n8k16.row.col.f32.bf16.bf16.f32 "
        "{%0,%1,%2,%3}, {%4,%5,%6,%7}, {%8,%9}, {%0,%1,%2,%3};"
        : "+f"(d[0]), "+f"(d[1]), "+f"(d[2]), "+f"(d[3])
        : "r"(a[0]), "r"(a[1]), "r"(a[2]), "r"(a[3]), "r"(b0), "r"(b1));
}
__device__ __forceinline__ void ldsm4(u32* r, u32 addr) {
    asm volatile("ldmatrix.sync.aligned.m8n8.x4.shared.b16 {%0,%1,%2,%3}, [%4];"
        : "=r"(r[0]), "=r"(r[1]), "=r"(r[2]), "=r"(r[3]) : "r"(addr));
}
__device__ __forceinline__ void ldsm4t(u32* r, u32 addr) {
    asm volatile("ldmatrix.sync.aligned.m8n8.x4.trans.shared.b16 {%0,%1,%2,%3}, [%4];"
        : "=r"(r[0]), "=r"(r[1]), "=r"(r[2]), "=r"(r[3]) : "r"(addr));
}
__device__ __forceinline__ u32 smem_u32(const void* p) {
    u32 a;
    asm("{ .reg .u64 t; cvta.to.shared.u64 t, %1; cvt.u32.u64 %0, t; }"
        : "=r"(a) : "l"(p));
    return a;
}
__device__ __forceinline__ void cpa16(u32 dst, const void* src) {
    asm volatile("cp.async.cg.shared.global [%0], [%1], 16;"
                 :: "r"(dst), "l"(src) : "memory");
}
__device__ __forceinline__ void cpa_commit() {
    asm volatile("cp.async.commit_group;" ::: "memory");
}
__device__ __forceinline__ void cpa_wait0() {
    asm volatile("cp.async.wait_group 0;" ::: "memory");
}

// ---------------- scratch ----------------
__device__ __nv_bfloat16 g_wh  [BB*HH*LP*DK];  // weight hi, [bh][512][64]
__device__ __nv_bfloat16 g_wl  [BB*HH*LP*DK];  // weight lo
__device__ __nv_bfloat16 g_vhh [BB*HH*LP*DK];  // vh hi
__device__ __nv_bfloat16 g_vhl [BB*HH*LP*DK];  // vh lo
__device__ __nv_bfloat16 g_w2h [LP*DK];        // w2^T hi, [j 512][d 64]
__device__ __nv_bfloat16 g_w2l [LP*DK];        // w2^T lo
__device__ float         g_o   [BB*LL*FF];     // attention out, [B,L,F]
__device__ __nv_bfloat16 g_wcth[FF*FF];        // Wcomb^T hi, [n][k]
__device__ __nv_bfloat16 g_wctl[FF*FF];
__device__ __nv_bfloat16 g_vsth[FF*FF];        // w_vs^T hi
__device__ __nv_bfloat16 g_vstl[FF*FF];
__device__ __nv_bfloat16 g_fcth[FF*FF];        // fc_w^T hi
__device__ __nv_bfloat16 g_fctl[FF*FF];

// ===========================================================================
// K0: Wcomb = w_qs . blockdiag(w1), TRANSPOSED + bf16 split: [n][k]
// ===========================================================================
__global__ void __launch_bounds__(256)
wcomb_kernel(const float* __restrict__ wqs, const float* __restrict__ w1,
             __nv_bfloat16* __restrict__ th, __nv_bfloat16* __restrict__ tl)
{
    __shared__ float w1s[64*64];
    const int tid = threadIdx.x;
    for (int i = tid; i < 4096; i += 256) w1s[i] = w1[i];
    __syncthreads();
    const int d = tid & 63, sub = tid >> 6;
    const int f = blockIdx.x * 4 + sub;
#pragma unroll
    for (int h = 0; h < 4; h++) {
        float acc = 0.f;
        const float* wr = &wqs[f*256 + h*64];
#pragma unroll 8
        for (int e = 0; e < 64; e++)
            acc = fmaf(wr[e], w1s[e*64 + d], acc);
        int n = h * 64 + d;
        __nv_bfloat16 hb = __float2bfloat16(acc);
        th[n*256 + f] = hb;
        tl[n*256 + f] = __float2bfloat16(acc - __bfloat162float(hb));
    }
}

// ===========================================================================
// K0b: generic transpose + split: out[n][k] = split(W[k][n]),  256x256
// ===========================================================================
__global__ void __launch_bounds__(256)
tsplit_kernel(const float* __restrict__ W,
              __nv_bfloat16* __restrict__ th, __nv_bfloat16* __restrict__ tl)
{
    const int n = blockIdx.x, k = threadIdx.x;
    float x = W[k*256 + n];
    __nv_bfloat16 hb = __float2bfloat16(x);
    th[n*256 + k] = hb;
    tl[n*256 + k] = __float2bfloat16(x - __bfloat162float(hb));
}

// ===========================================================================
// K0c: w2 transpose + bf16 split:  [j 512][d 64], j>=500 -> 0
// ===========================================================================
__global__ void __launch_bounds__(256)
w2prep_kernel(const float* __restrict__ w2,
              __nv_bfloat16* __restrict__ dh, __nv_bfloat16* __restrict__ dl)
{
    int idx = blockIdx.x * 256 + threadIdx.x;   // 512*64 total
    int j = idx >> 6, d = idx & 63;
    float x = (j < LL) ? w2[d * LL + j] : 0.f;
    __nv_bfloat16 hb = __float2bfloat16(x);
    dh[idx] = hb;
    dl[idx] = __float2bfloat16(x - __bfloat162float(hb));
}

// ===========================================================================
// K1: HMMA projection GEMM, double-buffered (cp.async for B, reg-prefetch A)
// CTA 128r x 128c (grid 250 x 2). 8 warps.
// dynamic smem: A stages [0,40960): AH(s)=s*20480, AL(s)=+10240
//               B stages [40960,81920): BH(s)=40960+s*20480, BL(s)=+10240
//               bias at 81920
// ===========================================================================
#define PJ_SMEM_BYTES 82432

template<bool RELU>
__global__ void __launch_bounds__(256)
projh_kernel(const float* __restrict__ A,
             const __nv_bfloat16* __restrict__ WTh, const __nv_bfloat16* __restrict__ WTl,
             const float* __restrict__ bias,
             __nv_bfloat16* __restrict__ dsth, __nv_bfloat16* __restrict__ dstl)
{
    extern __shared__ char smc[];
    const u32 smb = smem_u32(smc);
    float* biass = (float*)(smc + 81920);

    const int m0 = blockIdx.x * 128;
    const int n0 = blockIdx.y * 128;
    const int tid = threadIdx.x;
    const int w = tid >> 5, lane = tid & 31;

    if (RELU && tid < 64) biass[tid] = bias[tid];

    const int r8 = lane & 7, ti = lane >> 3;
    const int arow = r8 + ((ti & 1) << 3), acol = (ti >> 1) << 3;
    const int brow = r8 + ((ti >> 1) << 3), bcol = (ti & 1) << 3;

    const int ar = tid >> 1, hf = (tid & 1) * 16;
    const float* asrc = &A[(size_t)(m0 + ar) * 256 + hf];

    // ---- helpers ----
    auto issueB = [&](int kc, int stg) {
        const int k0 = kc * 32;
        const u32 bh = smb + 40960 + stg * 20480;
#pragma unroll
        for (int it = 0; it < 2; it++) {
            int idx = tid + it * 256;
            int rr = idx >> 2, qq = idx & 3;
            u32 off = (u32)(rr * 80 + qq * 16);
            cpa16(bh + off,         &WTh[(size_t)(n0 + rr) * 256 + k0 + qq * 8]);
            cpa16(bh + 10240 + off, &WTl[(size_t)(n0 + rr) * 256 + k0 + qq * 8]);
        }
    };
    float f[16];
    auto loadA = [&](int kc) {
        const float* s = asrc + kc * 32;
        *(float4*)&f[0]  = *(const float4*)&s[0];
        *(float4*)&f[4]  = *(const float4*)&s[4];
        *(float4*)&f[8]  = *(const float4*)&s[8];
        *(float4*)&f[12] = *(const float4*)&s[12];
    };
    auto storeA = [&](int stg) {
        u32 hp[8], lp[8];
#pragma unroll
        for (int i = 0; i < 8; i++) {
            hp[i] = packbf(f[2*i], f[2*i+1]);
            lp[i] = packbf(f[2*i] - bflo(hp[i]), f[2*i+1] - bfhi(hp[i]));
        }
        char* ah = smc + stg * 20480 + ar * 80 + hf * 2;
        *(uint4*)ah        = make_uint4(hp[0], hp[1], hp[2], hp[3]);
        *(uint4*)(ah + 16) = make_uint4(hp[4], hp[5], hp[6], hp[7]);
        char* al = ah + 10240;
        *(uint4*)al        = make_uint4(lp[0], lp[1], lp[2], lp[3]);
        *(uint4*)(al + 16) = make_uint4(lp[4], lp[5], lp[6], lp[7]);
    };

    float acc[16][4];
#pragma unroll
    for (int i = 0; i < 16; i++)
#pragma unroll
        for (int j = 0; j < 4; j++) acc[i][j] = 0.f;

    // ---- prologue: stage 0 ----
    issueB(0, 0); cpa_commit();
    loadA(0); storeA(0);
    cpa_wait0(); __syncthreads();

    for (int kc = 0; kc < 8; kc++) {
        const int cur = kc & 1;
        if (kc < 7) { issueB(kc + 1, 1 - cur); cpa_commit(); loadA(kc + 1); }

        const u32 sAh = smb + cur * 20480, sAl = sAh + 10240;
        const u32 sBh = smb + 40960 + cur * 20480, sBl = sBh + 10240;
#pragma unroll
        for (int ks = 0; ks < 2; ks++) {
            u32 a_h[4], a_l[4];
            const u32 aoff = (u32)((16*w + arow) * 80 + (ks*16 + acol) * 2);
            ldsm4(a_h, sAh + aoff);
            ldsm4(a_l, sAl + aoff);
#pragma unroll
            for (int np = 0; np < 8; np++) {
                u32 b_h[4], b_l[4];
                const u32 boff = (u32)((np*16 + brow) * 80 + (ks*16 + bcol) * 2);
                ldsm4(b_h, sBh + boff);
                ldsm4(b_l, sBl + boff);
                mma_bf16(acc[2*np],   a_h, b_h[0], b_h[1]);
                mma_bf16(acc[2*np],   a_h, b_l[0], b_l[1]);
                mma_bf16(acc[2*np],   a_l, b_h[0], b_h[1]);
                mma_bf16(acc[2*np+1], a_h, b_h[2], b_h[3]);
                mma_bf16(acc[2*np+1], a_h, b_l[2], b_l[3]);
                mma_bf16(acc[2*np+1], a_l, b_h[2], b_h[3]);
            }
        }
        if (kc < 7) storeA(1 - cur);
        cpa_wait0(); __syncthreads();
    }

    // ---- epilogue: bias/relu, split, permute to [bh][512][64] ----
    const int r0 = lane >> 2, ac = lane & 3;
#pragma unroll
    for (int e = 0; e < 2; e++) {
        const int row = m0 + 16*w + r0 + 8*e;
        const int b_ = row / LL;
        const int l  = row - b_ * LL;
#pragma unroll
        for (int nb = 0; nb < 16; nb++) {
            const int n = n0 + nb * 8 + 2 * ac;
            float v0 = acc[nb][2*e], v1 = acc[nb][2*e+1];
            if (RELU) {
                v0 += biass[n & 63]; v0 = v0 > 0.f ? v0 : 0.f;
                v1 += biass[(n & 63) + 1]; v1 = v1 > 0.f ? v1 : 0.f;
            }
            u32 hp = packbf(v0, v1);
            u32 lp = packbf(v0 - bflo(hp), v1 - bfhi(hp));
            size_t base = ((size_t)(b_ * HH + (n >> 6)) * LP + l) * DK + (n & 63);
            *(u32*)&dsth[base] = hp;
            *(u32*)&dstl[base] = lp;
        }
    }
}

// ===========================================================================
// K2: HMMA attention, double-buffered tiles via cp.async.
// stage s at s*73728: W2H+0, W2L+18432, VH+36864, VL+55296; b2 at 147456.
// ===========================================================================
#define AT_STG 73728
#define AT_W2H 0
#define AT_VH  36864
#define AT_B2  147456
#define ATTN_SMEM_BYTES 149504
#define TSTRB 144    // tile row stride bytes

__global__ void __launch_bounds__(256)
attn_kernel(const __nv_bfloat16* __restrict__ wh, const __nv_bfloat16* __restrict__ wl,
            const __nv_bfloat16* __restrict__ vhh, const __nv_bfloat16* __restrict__ vhl,
            const __nv_bfloat16* __restrict__ w2h, const __nv_bfloat16* __restrict__ w2l,
            const float* __restrict__ b2, float* __restrict__ O)
{
    extern __shared__ char smc[];
    const u32 smb = smem_u32(smc);
    float* b2f = (float*)(smc + AT_B2);

    const int tid  = threadIdx.x;
    const int w    = tid >> 5;
    const int lane = tid & 31;
    const int bh = blockIdx.y;
    const int b_ = bh >> 2, h = bh & 3;
    const int l0 = blockIdx.x * 128;

    const uint4* gw2h = (const uint4*)w2h;
    const uint4* gw2l = (const uint4*)w2l;
    const uint4* gvh  = (const uint4*)(vhh + (size_t)bh * LP * DK);
    const uint4* gvl  = (const uint4*)(vhl + (size_t)bh * LP * DK);

    auto issue = [&](int jtn, int stg) {
        const int rbase = jtn * 1024;
        const u32 dbase = smb + stg * AT_STG;
        for (int t = tid; t < 1024; t += 256) {
            int rr = t >> 3, qq = t & 7;
            u32 off = (u32)(rr * TSTRB + qq * 16);
            cpa16(dbase + AT_W2H + off,         gw2h + rbase + t);
            cpa16(dbase + AT_W2H + 18432 + off, gw2l + rbase + t);
            cpa16(dbase + AT_VH + off,          gvh + rbase + t);
            cpa16(dbase + AT_VH + 18432 + off,  gvl + rbase + t);
        }
    };

    // prologue: b2 + stage 0 + A fragments
    issue(0, 0); cpa_commit();
    for (int t = tid; t < 512; t += 256) b2f[t] = (t < LL) ? b2[t] : 0.f;

    const u32* awh = (const u32*)(wh + (size_t)bh * LP * DK);
    const u32* awl = (const u32*)(wl + (size_t)bh * LP * DK);
    const int arow = l0 + 16 * w + (lane >> 2);
    const int ac = lane & 3;
    u32 a_h[4][4], a_l[4][4];
#pragma unroll
    for (int ks = 0; ks < 4; ks++) {
        u32 i0 = (u32)(arow * 32 + ks * 8 + ac);
        a_h[ks][0] = awh[i0];           a_h[ks][1] = awh[i0 + 256];
        a_h[ks][2] = awh[i0 + 4];       a_h[ks][3] = awh[i0 + 260];
        a_l[ks][0] = awl[i0];           a_l[ks][1] = awl[i0 + 256];
        a_l[ks][2] = awl[i0 + 4];       a_l[ks][3] = awl[i0 + 260];
    }

    const int r8 = lane & 7, ti = lane >> 3;
    const u32 w2row = (u32)(r8 + ((ti >> 1) << 3));
    const u32 w2col = (u32)((ti & 1) << 3);
    const u32 vrow  = (u32)(r8 + ((ti & 1) << 3));
    const u32 vcol  = (u32)((ti >> 1) << 3);

    float oacc[8][4];
#pragma unroll
    for (int i = 0; i < 8; i++)
#pragma unroll
        for (int j = 0; j < 4; j++) oacc[i][j] = 0.f;
    float lsum0 = 0.f, lsum1 = 0.f;

    cpa_wait0(); __syncthreads();

    for (int jt = 0; jt < 4; jt++) {
        const int j0 = jt * 128;
        const int cur = jt & 1;
        const u32 sbase = smb + cur * AT_STG;

        if (jt < 3) { issue(jt + 1, 1 - cur); cpa_commit(); }

        // ---- S = A @ W2^T ----
        float sacc[16][4];
#pragma unroll
        for (int i = 0; i < 16; i++)
#pragma unroll
            for (int j = 0; j < 4; j++) sacc[i][j] = 0.f;

#pragma unroll
        for (int ks = 0; ks < 4; ks++) {
#pragma unroll
            for (int nbp = 0; nbp < 8; nbp++) {
                u32 addr_h = sbase + AT_W2H +
                    ((u32)(nbp*16) + w2row) * TSTRB + ((u32)(ks*16) + w2col) * 2;
                u32 addr_l = addr_h + 18432;
                u32 bh4[4], bl4[4];
                ldsm4(bh4, addr_h);
                ldsm4(bl4, addr_l);
                mma_bf16(sacc[2*nbp],   a_h[ks], bh4[0], bh4[1]);
                mma_bf16(sacc[2*nbp],   a_h[ks], bl4[0], bl4[1]);
                mma_bf16(sacc[2*nbp],   a_l[ks], bh4[0], bh4[1]);
                mma_bf16(sacc[2*nbp+1], a_h[ks], bh4[2], bh4[3]);
                mma_bf16(sacc[2*nbp+1], a_h[ks], bl4[2], bl4[3]);
                mma_bf16(sacc[2*nbp+1], a_l[ks], bh4[2], bh4[3]);
            }
        }

        // ---- P = exp(S + b2), pack to PV A-frags ----
        u32 pa_h[8][4], pa_l[8][4];
#pragma unroll
        for (int nb = 0; nb < 16; nb++) {
            const int ks = nb >> 1, hb = (nb & 1) * 2;
            const int col0 = nb * 8 + 2 * ac;
            const bool valid = (j0 + col0) < LL;
            const float bb0 = b2f[j0 + col0], bb1 = b2f[j0 + col0 + 1];
            float p0 = valid ? __expf(sacc[nb][0] + bb0) : 0.f;
            float p1 = valid ? __expf(sacc[nb][1] + bb1) : 0.f;
            float p2 = valid ? __expf(sacc[nb][2] + bb0) : 0.f;
            float p3 = valid ? __expf(sacc[nb][3] + bb1) : 0.f;
            lsum0 += p0 + p1; lsum1 += p2 + p3;
            u32 h01 = packbf(p0, p1), h23 = packbf(p2, p3);
            pa_h[ks][hb]   = h01;
            pa_h[ks][hb+1] = h23;
            pa_l[ks][hb]   = packbf(p0 - bflo(h01), p1 - bfhi(h01));
            pa_l[ks][hb+1] = packbf(p2 - bflo(h23), p3 - bfhi(h23));
        }

        // ---- O += P @ V ----
#pragma unroll
        for (int ks = 0; ks < 8; ks++) {
#pragma unroll
            for (int nbp = 0; nbp < 4; nbp++) {
                u32 addr_h = sbase + AT_VH +
                    ((u32)(ks*16) + vrow) * TSTRB + ((u32)(nbp*16) + vcol) * 2;
                u32 addr_l = addr_h + 18432;
                u32 vh4[4], vl4[4];
                ldsm4t(vh4, addr_h);
                ldsm4t(vl4, addr_l);
                mma_bf16(oacc[2*nbp],   pa_h[ks], vh4[0], vh4[1]);
                mma_bf16(oacc[2*nbp],   pa_h[ks], vl4[0], vl4[1]);
                mma_bf16(oacc[2*nbp],   pa_l[ks], vh4[0], vh4[1]);
                mma_bf16(oacc[2*nbp+1], pa_h[ks], vh4[2], vh4[3]);
                mma_bf16(oacc[2*nbp+1], pa_h[ks], vl4[2], vl4[3]);
                mma_bf16(oacc[2*nbp+1], pa_l[ks], vh4[2], vh4[3]);
            }
        }
        cpa_wait0(); __syncthreads();
    }

    lsum0 += __shfl_xor_sync(0xffffffffu, lsum0, 1);
    lsum0 += __shfl_xor_sync(0xffffffffu, lsum0, 2);
    lsum1 += __shfl_xor_sync(0xffffffffu, lsum1, 1);
    lsum1 += __shfl_xor_sync(0xffffffffu, lsum1, 2);
    const float inv0 = 1.f / lsum0, inv1 = 1.f / lsum1;

    const int r = lane >> 2;
    const int lA = l0 + 16 * w + r;
    const int lB = lA + 8;
#pragma unroll
    for (int cb = 0; cb < 8; cb++) {
        int col = h * 64 + cb * 8 + 2 * ac;
        if (lA < LL)
            *(float2*)&O[((size_t)(b_ * LL + lA)) * FF + col] =
                make_float2(oacc[cb][0] * inv0, oacc[cb][1] * inv0);
        if (lB < LL)
            *(float2*)&O[((size_t)(b_ * LL + lB)) * FF + col] =
                make_float2(oacc[cb][2] * inv1, oacc[cb][3] * inv1);
    }
}

// ===========================================================================
// K3: HMMA fc GEMM + residual + LayerNorm, double-buffered.
// dynamic smem: A stages [0,20480): AH(s)=s*10240, AL=+5120
//   B stages: BH(s)=20480+s*40960, BL=+20480  (ends 102400)
//   PS 102400, PQ 102912, SG 103424, SB 104448
// ===========================================================================
#define FC_SMEM_BYTES 105472

__global__ void __launch_bounds__(256)
fcln_kernel(const float* __restrict__ A,
            const __nv_bfloat16* __restrict__ WTh, const __nv_bfloat16* __restrict__ WTl,
            const float* __restrict__ Res, const float* __restrict__ lng,
            const float* __restrict__ lnb, float* __restrict__ Out)
{
    extern __shared__ char smc[];
    const u32 smb = smem_u32(smc);
    float* ps = (float*)(smc + 102400);
    float* pq = (float*)(smc + 102912);
    float* sg = (float*)(smc + 103424);
    float* sb = (float*)(smc + 104448);

    const int m0 = blockIdx.x * 64;
    const int tid = threadIdx.x;
    const int w = tid >> 5, lane = tid & 31;
    const int wr = w & 3, cg = w >> 2;

    sg[tid] = lng[tid]; sb[tid] = lnb[tid];

    const int r8 = lane & 7, ti = lane >> 3;
    const int arow = r8 + ((ti & 1) << 3), acol = (ti >> 1) << 3;
    const int brow = r8 + ((ti >> 1) << 3), bcol = (ti & 1) << 3;

    const int ar = tid >> 2, aq = (tid & 3) * 8;
    const float* asrc = &A[(size_t)(m0 + ar) * 256 + aq];

    auto issueB = [&](int kc, int stg) {
        const int k0 = kc * 32;
        const u32 bbh = smb + 20480 + stg * 40960;
#pragma unroll
        for (int it = 0; it < 4; it++) {
            int idx = tid + it * 256;
            int rr = idx >> 2, qq = idx & 3;
            u32 off = (u32)(rr * 80 + qq * 16);
            cpa16(bbh + off,         &WTh[(size_t)rr * 256 + k0 + qq * 8]);
            cpa16(bbh + 20480 + off, &WTl[(size_t)rr * 256 + k0 + qq * 8]);
        }
    };
    float f[8];
    auto loadA = [&](int kc) {
        const float* s = asrc + kc * 32;
        *(float4*)&f[0] = *(const float4*)&s[0];
        *(float4*)&f[4] = *(const float4*)&s[4];
    };
    auto storeA = [&](int stg) {
        u32 hp[4], lp[4];
#pragma unroll
        for (int i = 0; i < 4; i++) {
            hp[i] = packbf(f[2*i], f[2*i+1]);
            lp[i] = packbf(f[2*i] - bflo(hp[i]), f[2*i+1] - bfhi(hp[i]));
        }
        char* ah = smc + stg * 10240 + ar * 80 + aq * 2;
        *(uint4*)ah = make_uint4(hp[0], hp[1], hp[2], hp[3]);
        *(uint4*)(ah + 5120) = make_uint4(lp[0], lp[1], lp[2], lp[3]);
    };

    float acc[16][4];
#pragma unroll
    for (int i = 0; i < 16; i++)
#pragma unroll
        for (int j = 0; j < 4; j++) acc[i][j] = 0.f;

    issueB(0, 0); cpa_commit();
    loadA(0); storeA(0);
    cpa_wait0(); __syncthreads();

    for (int kc = 0; kc < 8; kc++) {
        const int cur = kc & 1;
        if (kc < 7) { issueB(kc + 1, 1 - cur); cpa_commit(); loadA(kc + 1); }

        const u32 sAh = smb + cur * 10240, sAl = sAh + 5120;
        const u32 sBh = smb + 20480 + cur * 40960, sBl = sBh + 20480;
#pragma unroll
        for (int ks = 0; ks < 2; ks++) {
            u32 a_h[4], a_l[4];
            const u32 aoff = (u32)((16*wr + arow) * 80 + (ks*16 + acol) * 2);
            ldsm4(a_h, sAh + aoff);
            ldsm4(a_l, sAl + aoff);
#pragma unroll
            for (int np = 0; np < 8; np++) {
                u32 b_h[4], b_l[4];
                const u32 boff = (u32)((cg*128 + np*16 + brow) * 80 + (ks*16 + bcol) * 2);
                ldsm4(b_h, sBh + boff);
                ldsm4(b_l, sBl + boff);
                mma_bf16(acc[2*np],   a_h, b_h[0], b_h[1]);
                mma_bf16(acc[2*np],   a_h, b_l[0], b_l[1]);
                mma_bf16(acc[2*np],   a_l, b_h[0], b_h[1]);
                mma_bf16(acc[2*np+1], a_h, b_h[2], b_h[3]);
                mma_bf16(acc[2*np+1], a_h, b_l[2], b_l[3]);
                mma_bf16(acc[2*np+1], a_l, b_h[2], b_h[3]);
            }
        }
        if (kc < 7) storeA(1 - cur);
        cpa_wait0(); __syncthreads();
    }

    // ---- epilogue: += residual, LN stats, normalize, store ----
    const int r0 = lane >> 2, ac = lane & 3;
    float s[2] = {0.f, 0.f}, q2[2] = {0.f, 0.f};
#pragma unroll
    for (int e = 0; e < 2; e++) {
        const int row = m0 + 16*wr + r0 + 8*e;
#pragma unroll
        for (int nb = 0; nb < 16; nb++) {
            const int col = cg*128 + nb*8 + 2*ac;
            float2 rv = *(const float2*)&Res[(size_t)row * 256 + col];
            acc[nb][2*e]   += rv.x;
            acc[nb][2*e+1] += rv.y;
            s[e]  += acc[nb][2*e] + acc[nb][2*e+1];
            q2[e] += acc[nb][2*e]*acc[nb][2*e] + acc[nb][2*e+1]*acc[nb][2*e+1];
        }
    }
#pragma unroll
    for (int e = 0; e < 2; e++) {
        s[e]  += __shfl_xor_sync(0xffffffffu, s[e], 1);
        s[e]  += __shfl_xor_sync(0xffffffffu, s[e], 2);
        q2[e] += __shfl_xor_sync(0xffffffffu, q2[e], 1);
        q2[e] += __shfl_xor_sync(0xffffffffu, q2[e], 2);
    }
    if (ac == 0) {
#pragma unroll
        for (int e = 0; e < 2; e++) {
            int rl = 16*wr + r0 + 8*e;
            ps[cg*64 + rl] = s[e];
            pq[cg*64 + rl] = q2[e];
        }
    }
    __syncthreads();
#pragma unroll
    for (int e = 0; e < 2; e++) {
        const int rl = 16*wr + r0 + 8*e;
        const int row = m0 + rl;
        const float sum = ps[rl] + ps[64 + rl];
        const float sq  = pq[rl] + pq[64 + rl];
        const float mu = sum * (1.f / 256.f);
        float var = sq * (1.f / 256.f) - mu * mu;
        var = var > 0.f ? var : 0.f;
        const float rstd = rsqrtf(var + 1e-6f);
#pragma unroll
        for (int nb = 0; nb < 16; nb++) {
            const int col = cg*128 + nb*8 + 2*ac;
            float o0 = (acc[nb][2*e]   - mu) * rstd * sg[col]     + sb[col];
            float o1 = (acc[nb][2*e+1] - mu) * rstd * sg[col + 1] + sb[col + 1];
            *(float2*)&Out[(size_t)row * 256 + col] = make_float2(o0, o1);
        }
    }
}

// ===========================================================================
// launch
// ===========================================================================
extern "C" void kernel_launch(void* const* d_in, const int* in_sizes, int n_in,
                              void* d_out, int out_size)
{
    const float* q    = (const float*)d_in[0];
    const float* v    = (const float*)d_in[2];
    const float* w_qs = (const float*)d_in[3];
    const float* w_vs = (const float*)d_in[4];
    const float* w1   = (const float*)d_in[5];
    const float* b1   = (const float*)d_in[6];
    const float* w2   = (const float*)d_in[7];
    const float* b2   = (const float*)d_in[8];
    const float* fc_w = (const float*)d_in[9];
    const float* ln_g = (const float*)d_in[10];
    const float* ln_b = (const float*)d_in[11];
    float* out = (float*)d_out;

    __nv_bfloat16 *wh, *wl, *vhh, *vhl, *w2h, *w2l;
    __nv_bfloat16 *wcth, *wctl, *vsth, *vstl, *fcth, *fctl;
    float *o;
    cudaGetSymbolAddress((void**)&wh,   g_wh);
    cudaGetSymbolAddress((void**)&wl,   g_wl);
    cudaGetSymbolAddress((void**)&vhh,  g_vhh);
    cudaGetSymbolAddress((void**)&vhl,  g_vhl);
    cudaGetSymbolAddress((void**)&w2h,  g_w2h);
    cudaGetSymbolAddress((void**)&w2l,  g_w2l);
    cudaGetSymbolAddress((void**)&o,    g_o);
    cudaGetSymbolAddress((void**)&wcth, g_wcth);
    cudaGetSymbolAddress((void**)&wctl, g_wctl);
    cudaGetSymbolAddress((void**)&vsth, g_vsth);
    cudaGetSymbolAddress((void**)&vstl, g_vstl);
    cudaGetSymbolAddress((void**)&fcth, g_fcth);
    cudaGetSymbolAddress((void**)&fctl, g_fctl);

    cudaFuncSetAttribute(attn_kernel, cudaFuncAttributeMaxDynamicSharedMemorySize,
                         ATTN_SMEM_BYTES);
    cudaFuncSetAttribute(fcln_kernel, cudaFuncAttributeMaxDynamicSharedMemorySize,
                         FC_SMEM_BYTES);
    cudaFuncSetAttribute(projh_kernel<true>, cudaFuncAttributeMaxDynamicSharedMemorySize,
                         PJ_SMEM_BYTES);
    cudaFuncSetAttribute(projh_kernel<false>, cudaFuncAttributeMaxDynamicSharedMemorySize,
                         PJ_SMEM_BYTES);

    wcomb_kernel<<<64, 256>>>(w_qs, w1, wcth, wctl);
    tsplit_kernel<<<256, 256>>>(w_vs, vsth, vstl);
    tsplit_kernel<<<256, 256>>>(fc_w, fcth, fctl);
    w2prep_kernel<<<128, 256>>>(w2, w2h, w2l);

    dim3 gProj(250, 2);
    projh_kernel<true ><<<gProj, 256, PJ_SMEM_BYTES>>>(q, wcth, wctl, b1, wh,  wl);
    projh_kernel<false><<<gProj, 256, PJ_SMEM_BYTES>>>(v, vsth, vstl, b1, vhh, vhl);

    dim3 gAttn(4, BB * HH);
    attn_kernel<<<gAttn, 256, ATTN_SMEM_BYTES>>>(wh, wl, vhh, vhl, w2h, w2l, b2, o);

    fcln_kernel<<<500, 256, FC_SMEM_BYTES>>>(o, fcth, fctl, q, ln_g, ln_b, out);
}